// round 1
// baseline (speedup 1.0000x reference)
#include <cuda_runtime.h>

#define NN 4
#define LL 4096
#define HH 12
#define DD 64
#define MM 64
#define NHNH (NN*HH)          // 48
#define TT 64                 // chunk length
#define CC (LL/TT)            // 64 chunks
#define EPSF 1e-6f

// Scratch (device globals -- no allocation allowed in kernel_launch)
__device__ float g_KV   [(size_t)NHNH*CC*DD*MM];  // per-chunk KV sums   (~50MB)
__device__ float g_KVpre[(size_t)NHNH*CC*DD*MM];  // exclusive prefixes  (~50MB)
__device__ float g_Ksum [(size_t)NHNH*CC*DD];
__device__ float g_Kpre [(size_t)NHNH*CC*DD];

__device__ __forceinline__ float phi(float x) {
    // elu(x) + 1
    return x > 0.f ? x + 1.f : __expf(x);
}

// ---------------------------------------------------------------------------
// Phase A: per-chunk KV = sum_l phi(k_l) v_l^T   and  Ksum = sum_l phi(k_l)
// grid = NH*C blocks (bx = nh*C + c), 256 threads
// ---------------------------------------------------------------------------
__global__ __launch_bounds__(256) void phaseA(const float* __restrict__ k,
                                              const float* __restrict__ v) {
    __shared__ float k_s[TT*64];
    __shared__ float v_s[TT*64];
    int bx = blockIdx.x;
    int c  = bx % CC, nh = bx / CC;
    int n  = nh / HH, h  = nh % HH;
    int l0 = c * TT;
    int t  = threadIdx.x;

    // load chunk (phi applied to k)
    for (int idx = t; idx < TT*16; idx += 256) {
        int l = idx >> 4, j = idx & 15;
        size_t gbase = ((size_t)(n*LL + l0 + l))*(HH*DD) + h*DD + j*4;
        float4 kf = *(const float4*)(k + gbase);
        kf.x = phi(kf.x); kf.y = phi(kf.y); kf.z = phi(kf.z); kf.w = phi(kf.w);
        *(float4*)(k_s + idx*4) = kf;
        *(float4*)(v_s + idx*4) = *(const float4*)(v + gbase);
    }
    __syncthreads();

    int r = t & 3, m = t >> 2;      // thread owns S[16r..16r+16)[m]
    float S[16];
#pragma unroll
    for (int i = 0; i < 16; i++) S[i] = 0.f;

    for (int l = 0; l < TT; l++) {
        float vm = v_s[l*64 + m];
        const float4* ks4 = (const float4*)(k_s + l*64 + r*16);
#pragma unroll
        for (int i = 0; i < 4; i++) {
            float4 kf = ks4[i];
            S[4*i+0] += kf.x * vm;
            S[4*i+1] += kf.y * vm;
            S[4*i+2] += kf.z * vm;
            S[4*i+3] += kf.w * vm;
        }
    }
    float* KVc = g_KV + (size_t)bx * 4096;
#pragma unroll
    for (int i = 0; i < 16; i++)
        KVc[(r*16 + i)*64 + m] = S[i];

    // Ksum (k_s untouched since load; no extra sync needed)
    if (t < 64) {
        float s = 0.f;
        for (int l = 0; l < TT; l++) s += k_s[l*64 + t];
        g_Ksum[(size_t)bx*64 + t] = s;
    }
}

// ---------------------------------------------------------------------------
// Phase B: exclusive prefix over chunks. grid = NH, 256 threads
// ---------------------------------------------------------------------------
__global__ __launch_bounds__(256) void phaseB() {
    int nh = blockIdx.x;
    int t  = threadIdx.x;
    float run[16];
#pragma unroll
    for (int i = 0; i < 16; i++) run[i] = 0.f;
    int e0 = t * 16;
    for (int c = 0; c < CC; c++) {
        size_t base = ((size_t)nh*CC + c)*4096 + e0;
#pragma unroll
        for (int i = 0; i < 16; i++) {
            g_KVpre[base + i] = run[i];
            run[i] += g_KV[base + i];
        }
    }
    if (t < 64) {
        float rs = 0.f;
        for (int c = 0; c < CC; c++) {
            size_t base = ((size_t)nh*CC + c)*64 + t;
            g_Kpre[base] = rs;
            rs += g_Ksum[base];
        }
    }
}

// ---------------------------------------------------------------------------
// Phase C: per-chunk scan from prefix state; o = qf.S, z = qf.kcum; out = o/z
// grid = NH*C blocks, 320 threads (256 main + 64 normalizer)
// ---------------------------------------------------------------------------
__global__ __launch_bounds__(320) void phaseC(const float* __restrict__ q,
                                              const float* __restrict__ k,
                                              const float* __restrict__ v,
                                              float* __restrict__ out) {
    extern __shared__ float smem[];
    float* q_s = smem;            // TT*64
    float* k_s = smem + 4096;     // TT*64
    float* v_s = smem + 8192;     // TT*64
    float* o_s = smem + 12288;    // TT*64
    float* z_s = smem + 16384;    // 2*TT

    int bx = blockIdx.x;
    int c  = bx % CC, nh = bx / CC;
    int n  = nh / HH, h  = nh % HH;
    int l0 = c * TT;
    int t  = threadIdx.x;

    for (int idx = t; idx < TT*16; idx += 320) {
        int l = idx >> 4, j = idx & 15;
        size_t gbase = ((size_t)(n*LL + l0 + l))*(HH*DD) + h*DD + j*4;
        float4 a = *(const float4*)(q + gbase);
        a.x = phi(a.x); a.y = phi(a.y); a.z = phi(a.z); a.w = phi(a.w);
        *(float4*)(q_s + idx*4) = a;
        float4 b = *(const float4*)(k + gbase);
        b.x = phi(b.x); b.y = phi(b.y); b.z = phi(b.z); b.w = phi(b.w);
        *(float4*)(k_s + idx*4) = b;
        *(float4*)(v_s + idx*4) = *(const float4*)(v + gbase);
    }
    __syncthreads();

    if (t < 256) {
        int r = t & 3, m = t >> 2;          // 4 partners are consecutive lanes
        float S[16];
        const float* KVp = g_KVpre + (size_t)bx * 4096;
#pragma unroll
        for (int i = 0; i < 16; i++) S[i] = KVp[(r*16 + i)*64 + m];

        for (int l = 0; l < TT; l++) {
            float vm = v_s[l*64 + m];
            const float4* ks4 = (const float4*)(k_s + l*64 + r*16);
            const float4* qs4 = (const float4*)(q_s + l*64 + r*16);
            float o0 = 0.f, o1 = 0.f, o2 = 0.f, o3 = 0.f;
#pragma unroll
            for (int i = 0; i < 4; i++) {
                float4 kf = ks4[i], qf = qs4[i];
                S[4*i+0] += kf.x * vm;  o0 += qf.x * S[4*i+0];
                S[4*i+1] += kf.y * vm;  o1 += qf.y * S[4*i+1];
                S[4*i+2] += kf.z * vm;  o2 += qf.z * S[4*i+2];
                S[4*i+3] += kf.w * vm;  o3 += qf.w * S[4*i+3];
            }
            float o = (o0 + o1) + (o2 + o3);
            o += __shfl_xor_sync(0xffffffffu, o, 1);
            o += __shfl_xor_sync(0xffffffffu, o, 2);
            if (r == 0) o_s[l*64 + m] = o;
        }
    } else {
        // normalizer warps: z_l = qf_l . (Kpre + inclusive cumsum of kf)
        int tz   = t - 256;                 // d = tz in [0,64)
        int lane = tz & 31, w = tz >> 5;
        float kcum = g_Kpre[(size_t)bx*64 + tz];
        for (int l = 0; l < TT; l++) {
            kcum += k_s[l*64 + tz];
            float zp = q_s[l*64 + tz] * kcum;
            zp += __shfl_xor_sync(0xffffffffu, zp, 16);
            zp += __shfl_xor_sync(0xffffffffu, zp, 8);
            zp += __shfl_xor_sync(0xffffffffu, zp, 4);
            zp += __shfl_xor_sync(0xffffffffu, zp, 2);
            zp += __shfl_xor_sync(0xffffffffu, zp, 1);
            if (lane == 0) z_s[w*TT + l] = zp;
        }
    }
    __syncthreads();

    for (int idx = t; idx < TT*64; idx += 320) {
        int l = idx >> 6, m = idx & 63;
        float z = z_s[l] + z_s[TT + l] + EPSF;
        out[((size_t)(n*LL + l0 + l))*(HH*MM) + h*MM + m] = o_s[idx] / z;
    }
}

// ---------------------------------------------------------------------------
extern "C" void kernel_launch(void* const* d_in, const int* in_sizes, int n_in,
                              void* d_out, int out_size) {
    const float* q = (const float*)d_in[0];
    const float* k = (const float*)d_in[1];
    const float* v = (const float*)d_in[2];
    float* out = (float*)d_out;

    const int smemC = (16384 + 2*TT) * (int)sizeof(float);   // 66048 B
    cudaFuncSetAttribute(phaseC, cudaFuncAttributeMaxDynamicSharedMemorySize, smemC);

    phaseA<<<NHNH*CC, 256>>>(k, v);
    phaseB<<<NHNH, 256>>>();
    phaseC<<<NHNH*CC, 320, smemC>>>(q, k, v, out);
}

// round 2
// speedup vs baseline: 2.7564x; 2.7564x over previous
#include <cuda_runtime.h>

#define NN 4
#define LL 4096
#define HH 12
#define DD 64
#define MM 64
#define NHNH 48
#define TT 64
#define CC 64
#define HD 768            // H*D row stride
#define EPSF 1e-6f
#define QP 65             // padded row stride for scalar-access tiles

// Scratch (device globals -- no allocation allowed)
__device__ float g_KV   [(size_t)NHNH*CC*4096];   // per-chunk KV sums
__device__ float g_KVpre[(size_t)NHNH*CC*4096];   // exclusive prefixes
__device__ float g_Ksum [(size_t)NHNH*CC*64];
__device__ float g_Kpre [(size_t)NHNH*CC*64];

__device__ __forceinline__ float phi(float x) {  // elu(x)+1
    return x > 0.f ? x + 1.f : __expf(x);
}

// ---------------------------------------------------------------------------
// Phase A: KV_c[d][m] = sum_s phi(k)[s][d] * v[s][m]   (64x64x64 GEMM)
//          Ksum_c[d]  = sum_s phi(k)[s][d]
// grid = NH*C, 256 threads, 4x4 register tiles
// ---------------------------------------------------------------------------
__global__ __launch_bounds__(256) void phaseA(const float* __restrict__ k,
                                              const float* __restrict__ v) {
    __shared__ float k_s[64*64];
    __shared__ float v_s[64*64];
    int bx = blockIdx.x;
    int c  = bx & 63, nh = bx >> 6;
    int n  = nh / HH, h  = nh % HH;
    int l0 = c * TT;
    int t  = threadIdx.x;

    for (int idx = t; idx < 1024; idx += 256) {
        int s = idx >> 4, j = (idx & 15) << 2;
        size_t g = ((size_t)(n*LL + l0 + s))*HD + h*DD + j;
        float4 kf = *(const float4*)(k + g);
        kf.x = phi(kf.x); kf.y = phi(kf.y); kf.z = phi(kf.z); kf.w = phi(kf.w);
        *(float4*)(k_s + s*64 + j) = kf;
        *(float4*)(v_s + s*64 + j) = *(const float4*)(v + g);
    }
    __syncthreads();

    int lane = t & 31, w = t >> 5;
    int i0 = (w >> 1)*16 + (lane >> 3)*4;   // d
    int j0 = (w & 1)*32 + (lane & 7)*4;     // m

    float acc[4][4];
#pragma unroll
    for (int a = 0; a < 4; a++)
#pragma unroll
        for (int b = 0; b < 4; b++) acc[a][b] = 0.f;

#pragma unroll 8
    for (int s = 0; s < 64; s++) {
        float4 a4 = *(const float4*)(k_s + s*64 + i0);
        float4 b4 = *(const float4*)(v_s + s*64 + j0);
        float av[4] = {a4.x, a4.y, a4.z, a4.w};
        float bv[4] = {b4.x, b4.y, b4.z, b4.w};
#pragma unroll
        for (int ii = 0; ii < 4; ii++)
#pragma unroll
            for (int jj = 0; jj < 4; jj++)
                acc[ii][jj] += av[ii] * bv[jj];
    }

    float* KVb = g_KV + (size_t)bx * 4096;
#pragma unroll
    for (int ii = 0; ii < 4; ii++)
        *(float4*)(KVb + (i0+ii)*64 + j0) =
            make_float4(acc[ii][0], acc[ii][1], acc[ii][2], acc[ii][3]);

    if (t < 64) {
        float s0 = 0.f;
#pragma unroll 8
        for (int s = 0; s < 64; s++) s0 += k_s[s*64 + t];
        g_Ksum[(size_t)bx*64 + t] = s0;
    }
}

// ---------------------------------------------------------------------------
// Phase B: exclusive prefix over chunks, one state element per thread.
// grid = 768 (KV: 48*4096 elems) + 12 (Ksum: 48*64 elems)
// ---------------------------------------------------------------------------
__global__ __launch_bounds__(256) void phaseB() {
    int b = blockIdx.x;
    if (b < 768) {
        int gid = b*256 + threadIdx.x;          // 0..196607
        int e = gid & 4095, nh = gid >> 12;
        size_t base = ((size_t)nh*CC)*4096 + e;
        float run = 0.f;
#pragma unroll 8
        for (int c = 0; c < CC; c++) {
            float x = g_KV[base + (size_t)c*4096];
            g_KVpre[base + (size_t)c*4096] = run;
            run += x;
        }
    } else {
        int gid = (b - 768)*256 + threadIdx.x;  // 0..3071
        int e = gid & 63, nh = gid >> 6;
        size_t base = ((size_t)nh*CC)*64 + e;
        float run = 0.f;
#pragma unroll 8
        for (int c = 0; c < CC; c++) {
            float x = g_Ksum[base + c*64];
            g_Kpre[base + c*64] = run;
            run += x;
        }
    }
}

// ---------------------------------------------------------------------------
// Phase C: P = tril(Qf Kf^T);  O = Qf*S_pre + P*V;  z = Qf.Kpre + rowsum(P)
// grid = NH*C, 256 threads, dynamic smem
// ---------------------------------------------------------------------------
__global__ __launch_bounds__(256) void phaseC(const float* __restrict__ q,
                                              const float* __restrict__ k,
                                              const float* __restrict__ v,
                                              float* __restrict__ out) {
    extern __shared__ float sm[];
    float* q_s  = sm;                 // 64*65 scalar-access, phi applied
    float* P_s  = q_s + 64*QP;        // 64*65
    float* kT   = P_s + 64*QP;        // 64*64 transposed [d][s], phi applied
    float* v_s  = kT  + 4096;         // 64*64
    float* S_s  = v_s + 4096;         // 64*64 prefix state [d][m]
    float* Kpre = S_s + 4096;         // 64
    float* z_s  = Kpre + 64;          // 64

    int bx = blockIdx.x;
    int c  = bx & 63, nh = bx >> 6;
    int n  = nh / HH, h  = nh % HH;
    int l0 = c * TT;
    int t  = threadIdx.x;

    // q (phi, padded scalar layout) and v (row-major float4)
    for (int idx = t; idx < 1024; idx += 256) {
        int l = idx >> 4, j = (idx & 15) << 2;
        size_t g = ((size_t)(n*LL + l0 + l))*HD + h*DD + j;
        float4 a = *(const float4*)(q + g);
        q_s[l*QP + j+0] = phi(a.x);
        q_s[l*QP + j+1] = phi(a.y);
        q_s[l*QP + j+2] = phi(a.z);
        q_s[l*QP + j+3] = phi(a.w);
        *(float4*)(v_s + l*64 + j) = *(const float4*)(v + g);
    }
    // k transposed into [d][s] (lanes span s -> conflict-free STS)
    for (int idx = t; idx < 1024; idx += 256) {
        int s = idx & 63, db = idx >> 6;  // db 0..15
        size_t g = ((size_t)(n*LL + l0 + s))*HD + h*DD + db*4;
        float4 a = *(const float4*)(k + g);
        kT[(db*4+0)*64 + s] = phi(a.x);
        kT[(db*4+1)*64 + s] = phi(a.y);
        kT[(db*4+2)*64 + s] = phi(a.z);
        kT[(db*4+3)*64 + s] = phi(a.w);
    }
    // prefix state + Kpre
    {
        const float* KVp = g_KVpre + (size_t)bx * 4096;
        for (int idx = t; idx < 1024; idx += 256)
            *(float4*)(S_s + idx*4) = *(const float4*)(KVp + idx*4);
        if (t < 64) Kpre[t] = g_Kpre[(size_t)bx*64 + t];
    }
    __syncthreads();

    int lane = t & 31, w = t >> 5;
    int i0 = (w >> 1)*16 + (lane >> 3)*4;   // l
    int j0 = (w & 1)*32 + (lane & 7)*4;     // s (GEMM1) / m (GEMM0/2)

    float pacc[4][4], oacc[4][4];
#pragma unroll
    for (int a = 0; a < 4; a++)
#pragma unroll
        for (int b = 0; b < 4; b++) { pacc[a][b] = 0.f; oacc[a][b] = 0.f; }

    // Fused GEMM1 (P = Qf Kf^T) + GEMM0 (O += Qf S_pre): shared A-loads over d
#pragma unroll 4
    for (int d = 0; d < 64; d++) {
        float av[4];
#pragma unroll
        for (int ii = 0; ii < 4; ii++) av[ii] = q_s[(i0+ii)*QP + d];
        float4 b4 = *(const float4*)(kT  + d*64 + j0);
        float4 c4 = *(const float4*)(S_s + d*64 + j0);
        float bv[4] = {b4.x, b4.y, b4.z, b4.w};
        float cv[4] = {c4.x, c4.y, c4.z, c4.w};
#pragma unroll
        for (int ii = 0; ii < 4; ii++)
#pragma unroll
            for (int jj = 0; jj < 4; jj++) {
                pacc[ii][jj] += av[ii] * bv[jj];
                oacc[ii][jj] += av[ii] * cv[jj];
            }
    }

    // causal mask (keep s <= l) and store P
#pragma unroll
    for (int ii = 0; ii < 4; ii++)
#pragma unroll
        for (int jj = 0; jj < 4; jj++)
            P_s[(i0+ii)*QP + j0+jj] = (j0+jj <= i0+ii) ? pacc[ii][jj] : 0.f;
    __syncthreads();

    // z_l = rowsum(P) + Qf_l . Kpre  (+ eps)
    if (t < 64) {
        float zr = 0.f;
#pragma unroll 8
        for (int s = 0; s < 64; s++) zr += P_s[t*QP + s];
#pragma unroll 8
        for (int d = 0; d < 64; d++) zr += q_s[t*QP + d] * Kpre[d];
        z_s[t] = zr + EPSF;
    }
    __syncthreads();

    // GEMM2: O += P * V  (over s)
#pragma unroll 4
    for (int s = 0; s < 64; s++) {
        float av[4];
#pragma unroll
        for (int ii = 0; ii < 4; ii++) av[ii] = P_s[(i0+ii)*QP + s];
        float4 b4 = *(const float4*)(v_s + s*64 + j0);
        float bv[4] = {b4.x, b4.y, b4.z, b4.w};
#pragma unroll
        for (int ii = 0; ii < 4; ii++)
#pragma unroll
            for (int jj = 0; jj < 4; jj++)
                oacc[ii][jj] += av[ii] * bv[jj];
    }

    // out = O / z
#pragma unroll
    for (int ii = 0; ii < 4; ii++) {
        float rz = 1.f / z_s[i0+ii];
        size_t g = ((size_t)(n*LL + l0 + i0 + ii))*HD + h*DD + j0;
        *(float4*)(out + g) = make_float4(oacc[ii][0]*rz, oacc[ii][1]*rz,
                                          oacc[ii][2]*rz, oacc[ii][3]*rz);
    }
}

// ---------------------------------------------------------------------------
extern "C" void kernel_launch(void* const* d_in, const int* in_sizes, int n_in,
                              void* d_out, int out_size) {
    const float* q = (const float*)d_in[0];
    const float* k = (const float*)d_in[1];
    const float* v = (const float*)d_in[2];
    float* out = (float*)d_out;

    const int smemC = (64*QP*2 + 3*4096 + 128) * (int)sizeof(float);  // 82944 B
    cudaFuncSetAttribute(phaseC, cudaFuncAttributeMaxDynamicSharedMemorySize, smemC);

    phaseA<<<NHNH*CC, 256>>>(k, v);
    phaseB<<<780, 256>>>();
    phaseC<<<NHNH*CC, 256, smemC>>>(q, k, v, out);
}

// round 3
// speedup vs baseline: 3.4213x; 1.2412x over previous
#include <cuda_runtime.h>

#define NN 4
#define LL 4096
#define HH 12
#define NHNH 48
#define TT 64
#define CC 64
#define HD 768
#define EPSF 1e-6f

// Scratch (device globals; phaseB turns g_KV into exclusive prefixes in-place)
__device__ float g_KV[(size_t)NHNH*CC*4096];
__device__ float g_Ks[(size_t)NHNH*CC*64];

__device__ __forceinline__ float phi(float x) { return x > 0.f ? x + 1.f : __expf(x); }
__device__ __forceinline__ unsigned cvt_tf32(float x) {
    unsigned u; asm("cvt.rna.tf32.f32 %0, %1;" : "=r"(u) : "f"(x)); return u;
}
__device__ __forceinline__ float tf32f(float x) { return __uint_as_float(cvt_tf32(x)); }
__device__ __forceinline__ float phi_tf32(float x) { return tf32f(phi(x)); }

// Swizzled indices for 64-stride tiles (conflict-free fragment access)
__device__ __forceinline__ int ASW(int r, int c) { return r*64 + (c ^ ((r & 7) << 2)); }  // A: row-major MxK
__device__ __forceinline__ int BSW(int k, int n) { return k*64 + (n ^ ((k & 3) << 3)); }  // B: [K][N]

__device__ __forceinline__ void mma8(float* d, const unsigned* a, const unsigned* b) {
    asm volatile(
        "mma.sync.aligned.m16n8k8.row.col.f32.tf32.tf32.f32 "
        "{%0,%1,%2,%3},{%4,%5,%6,%7},{%8,%9},{%0,%1,%2,%3};\n"
        : "+f"(d[0]), "+f"(d[1]), "+f"(d[2]), "+f"(d[3])
        : "r"(a[0]), "r"(a[1]), "r"(a[2]), "r"(a[3]), "r"(b[0]), "r"(b[1]));
}

__device__ __forceinline__ void ldA(unsigned* a, const float* base, int r0, int k0, int lane) {
    int row = r0 + (lane >> 2), col = k0 + (lane & 3);
    a[0] = __float_as_uint(base[ASW(row,     col)]);
    a[1] = __float_as_uint(base[ASW(row + 8, col)]);
    a[2] = __float_as_uint(base[ASW(row,     col + 4)]);
    a[3] = __float_as_uint(base[ASW(row + 8, col + 4)]);
}
__device__ __forceinline__ void ldB(unsigned* b, const float* base, int k0, int n0, int lane) {
    int kk = k0 + (lane & 3), n = n0 + (lane >> 2);
    b[0] = __float_as_uint(base[BSW(kk,     n)]);
    b[1] = __float_as_uint(base[BSW(kk + 4, n)]);
}

// ---------------------------------------------------------------------------
// Phase A: KV_c[d][m] = sum_s phi(k)[s][d] * v[s][m]  via tf32 mma
//          Ks_c[d]    = sum_s phi(k)[s][d]
// ---------------------------------------------------------------------------
__global__ __launch_bounds__(256) void phaseA(const float* __restrict__ k,
                                              const float* __restrict__ v) {
    __shared__ float kT[4096];   // A-style swizzle, [d][s], phi+tf32
    __shared__ float v_s[4096];  // B-style swizzle, [s][m], tf32
    int bx = blockIdx.x;
    int c = bx & 63, nh = bx >> 6;
    int n = nh / HH, h = nh % HH;
    int l0 = c * TT;
    int t = threadIdx.x, lane = t & 31, w = t >> 5;

    for (int idx = t; idx < 1024; idx += 256) {
        int s = idx >> 4, j = (idx & 15) << 2;
        size_t g = ((size_t)(n*LL + l0 + s))*HD + h*64 + j;
        float4 b = *(const float4*)(v + g);
        b.x = tf32f(b.x); b.y = tf32f(b.y); b.z = tf32f(b.z); b.w = tf32f(b.w);
        *(float4*)(v_s + s*64 + (j ^ ((s & 3) << 3))) = b;
    }
    for (int idx = t; idx < 1024; idx += 256) {
        int s = idx & 63, db = idx >> 6;             // d = db*4 .. +3
        size_t g = ((size_t)(n*LL + l0 + s))*HD + h*64 + db*4;
        float4 a = *(const float4*)(k + g);
        kT[ASW(db*4 + 0, s)] = phi_tf32(a.x);
        kT[ASW(db*4 + 1, s)] = phi_tf32(a.y);
        kT[ASW(db*4 + 2, s)] = phi_tf32(a.z);
        kT[ASW(db*4 + 3, s)] = phi_tf32(a.w);
    }
    __syncthreads();

    int r0 = (w >> 1) * 16;       // d strip
    int n0c = (w & 1) * 32;       // m strip
    float acc[4][4];
#pragma unroll
    for (int i = 0; i < 4; i++)
#pragma unroll
        for (int j = 0; j < 4; j++) acc[i][j] = 0.f;

#pragma unroll
    for (int k0 = 0; k0 < 64; k0 += 8) {
        unsigned a[4]; ldA(a, kT, r0, k0, lane);
#pragma unroll
        for (int nt = 0; nt < 4; nt++) {
            unsigned b[2]; ldB(b, v_s, k0, n0c + nt*8, lane);
            mma8(acc[nt], a, b);
        }
    }

    float* KVb = g_KV + (size_t)bx * 4096;
    int rowb = r0 + (lane >> 2);
#pragma unroll
    for (int nt = 0; nt < 4; nt++) {
        int col = n0c + nt*8 + (lane & 3)*2;
        *(float2*)(KVb + rowb*64 + col)     = make_float2(acc[nt][0], acc[nt][1]);
        *(float2*)(KVb + (rowb+8)*64 + col) = make_float2(acc[nt][2], acc[nt][3]);
    }

    if (t < 64) {
        float s0 = 0.f;
#pragma unroll 8
        for (int s = 0; s < 64; s++) s0 += kT[ASW(t, s)];
        g_Ks[(size_t)bx*64 + t] = s0;
    }
}

// ---------------------------------------------------------------------------
// Phase B: in-place exclusive prefix over chunks (one element per thread)
// ---------------------------------------------------------------------------
__global__ __launch_bounds__(256) void phaseB() {
    int b = blockIdx.x;
    if (b < 768) {
        int gid = b*256 + threadIdx.x;
        int e = gid & 4095, nh = gid >> 12;
        size_t base = ((size_t)nh*CC)*4096 + e;
        float run = 0.f;
#pragma unroll 8
        for (int c = 0; c < CC; c++) {
            float x = g_KV[base + (size_t)c*4096];
            g_KV[base + (size_t)c*4096] = run;
            run += x;
        }
    } else {
        int gid = (b - 768)*256 + threadIdx.x;
        int e = gid & 63, nh = gid >> 6;
        size_t base = ((size_t)nh*CC)*64 + e;
        float run = 0.f;
#pragma unroll 8
        for (int c = 0; c < CC; c++) {
            float x = g_Ks[base + c*64];
            g_Ks[base + c*64] = run;
            run += x;
        }
    }
}

// ---------------------------------------------------------------------------
// Phase C: P = tril(Qf Kf^T); O = Qf*S_pre + P*V; z = rowsum(P) + Qf.Kpre
// all GEMMs via tf32 mma
// ---------------------------------------------------------------------------
__global__ __launch_bounds__(256) void phaseC(const float* __restrict__ q,
                                              const float* __restrict__ k,
                                              const float* __restrict__ v,
                                              float* __restrict__ out) {
    extern __shared__ float sm[];
    float* q_s  = sm;               // A-style [l][d], phi+tf32
    float* kT   = q_s  + 4096;      // B-style [d][s], phi+tf32
    float* v_s  = kT   + 4096;      // B-style [s][m], tf32
    float* S_s  = v_s  + 4096;      // B-style [d][m], tf32
    float* P_s  = S_s  + 4096;      // A-style [l][s], tf32 (masked)
    float* Kpre = P_s  + 4096;      // 64
    float* z_s  = Kpre + 64;        // 64

    int bx = blockIdx.x;
    int c = bx & 63, nh = bx >> 6;
    int n = nh / HH, h = nh % HH;
    int l0 = c * TT;
    int t = threadIdx.x, lane = t & 31, w = t >> 5;

    for (int idx = t; idx < 1024; idx += 256) {
        int l = idx >> 4, j = (idx & 15) << 2;
        size_t g = ((size_t)(n*LL + l0 + l))*HD + h*64 + j;
        float4 a = *(const float4*)(q + g);
        a.x = phi_tf32(a.x); a.y = phi_tf32(a.y); a.z = phi_tf32(a.z); a.w = phi_tf32(a.w);
        *(float4*)(q_s + l*64 + (j ^ ((l & 7) << 2))) = a;
        float4 b = *(const float4*)(v + g);
        b.x = tf32f(b.x); b.y = tf32f(b.y); b.z = tf32f(b.z); b.w = tf32f(b.w);
        *(float4*)(v_s + l*64 + (j ^ ((l & 3) << 3))) = b;
    }
    for (int idx = t; idx < 1024; idx += 256) {
        int s = idx & 63, db = idx >> 6;
        size_t g = ((size_t)(n*LL + l0 + s))*HD + h*64 + db*4;
        float4 a = *(const float4*)(k + g);
        kT[BSW(db*4 + 0, s)] = phi_tf32(a.x);
        kT[BSW(db*4 + 1, s)] = phi_tf32(a.y);
        kT[BSW(db*4 + 2, s)] = phi_tf32(a.z);
        kT[BSW(db*4 + 3, s)] = phi_tf32(a.w);
    }
    {
        const float* KVp = g_KV + (size_t)bx * 4096;
        for (int idx = t; idx < 1024; idx += 256) {
            int d = idx >> 4, j = (idx & 15) << 2;
            float4 a = *(const float4*)(KVp + d*64 + j);
            a.x = tf32f(a.x); a.y = tf32f(a.y); a.z = tf32f(a.z); a.w = tf32f(a.w);
            *(float4*)(S_s + d*64 + (j ^ ((d & 3) << 3))) = a;
        }
        if (t < 64) Kpre[t] = g_Ks[(size_t)bx*64 + t];
    }
    __syncthreads();

    int r0 = (w >> 1) * 16;     // l strip
    int n0c = (w & 1) * 32;     // s / m strip
    float pacc[4][4], oacc[4][4];
#pragma unroll
    for (int i = 0; i < 4; i++)
#pragma unroll
        for (int j = 0; j < 4; j++) { pacc[i][j] = 0.f; oacc[i][j] = 0.f; }

    // fused: P = Qf Kf^T  and  O = Qf S_pre (shared A fragments)
#pragma unroll
    for (int k0 = 0; k0 < 64; k0 += 8) {
        unsigned a[4]; ldA(a, q_s, r0, k0, lane);
#pragma unroll
        for (int nt = 0; nt < 4; nt++) {
            unsigned bk[2]; ldB(bk, kT,  k0, n0c + nt*8, lane);
            mma8(pacc[nt], a, bk);
            unsigned bs[2]; ldB(bs, S_s, k0, n0c + nt*8, lane);
            mma8(oacc[nt], a, bs);
        }
    }

    // causal mask + tf32 requantize + store P
    {
        int rowb = r0 + (lane >> 2);
#pragma unroll
        for (int nt = 0; nt < 4; nt++) {
            int colb = n0c + nt*8 + (lane & 3)*2;
#pragma unroll
            for (int half = 0; half < 2; half++) {
                int row = rowb + 8*half;
                float p0 = (colb     <= row) ? pacc[nt][2*half]     : 0.f;
                float p1 = (colb + 1 <= row) ? pacc[nt][2*half + 1] : 0.f;
                P_s[ASW(row, colb)]     = tf32f(p0);
                P_s[ASW(row, colb + 1)] = tf32f(p1);
            }
        }
    }
    __syncthreads();

    // z_l = rowsum(P) + Qf_l . Kpre + eps
    if (t < 64) {
        float zr = EPSF;
#pragma unroll 8
        for (int s = 0; s < 64; s++) zr += P_s[ASW(t, s)];
#pragma unroll 8
        for (int d = 0; d < 64; d++) zr += q_s[ASW(t, d)] * Kpre[d];
        z_s[t] = zr;
    }

    // O += P V
#pragma unroll
    for (int k0 = 0; k0 < 64; k0 += 8) {
        unsigned a[4]; ldA(a, P_s, r0, k0, lane);
#pragma unroll
        for (int nt = 0; nt < 4; nt++) {
            unsigned b[2]; ldB(b, v_s, k0, n0c + nt*8, lane);
            mma8(oacc[nt], a, b);
        }
    }
    __syncthreads();

    // out = O / z
    {
        int rowb = r0 + (lane >> 2);
        float rz0 = __frcp_rn(z_s[rowb]);
        float rz1 = __frcp_rn(z_s[rowb + 8]);
#pragma unroll
        for (int nt = 0; nt < 4; nt++) {
            int col = n0c + nt*8 + (lane & 3)*2;
            size_t g0 = ((size_t)(n*LL + l0 + rowb))*HD + h*64 + col;
            size_t g1 = ((size_t)(n*LL + l0 + rowb + 8))*HD + h*64 + col;
            *(float2*)(out + g0) = make_float2(oacc[nt][0]*rz0, oacc[nt][1]*rz0);
            *(float2*)(out + g1) = make_float2(oacc[nt][2]*rz1, oacc[nt][3]*rz1);
        }
    }
}

// ---------------------------------------------------------------------------
extern "C" void kernel_launch(void* const* d_in, const int* in_sizes, int n_in,
                              void* d_out, int out_size) {
    const float* q = (const float*)d_in[0];
    const float* k = (const float*)d_in[1];
    const float* v = (const float*)d_in[2];
    float* out = (float*)d_out;

    const int smemC = (5*4096 + 128) * (int)sizeof(float);   // 82944 B
    cudaFuncSetAttribute(phaseC, cudaFuncAttributeMaxDynamicSharedMemorySize, smemC);

    phaseA<<<NHNH*CC, 256>>>(k, v);
    phaseB<<<780, 256>>>();
    phaseC<<<NHNH*CC, 256, smemC>>>(q, k, v, out);
}

// round 4
// speedup vs baseline: 3.5785x; 1.0460x over previous
#include <cuda_runtime.h>

#define NN 4
#define LL 4096
#define HH 12
#define NHNH 48
#define TT 64
#define CC 64
#define HD 768
#define EPSF 1e-6f
#define SA 76   // stride for A-layout / [n][k]-indexed tiles (76 % 32 == 12)
#define SB 72   // stride for [k][n]-indexed tiles         (72 % 32 == 8)

// Scratch (device globals; phaseB turns g_KV into exclusive prefixes in-place)
__device__ float g_KV[(size_t)NHNH*CC*4096];
__device__ float g_Ks[(size_t)NHNH*CC*64];

__device__ __forceinline__ float phi(float x) { return x > 0.f ? x + 1.f : __expf(x); }
__device__ __forceinline__ unsigned cvt_tf32(float x) {
    unsigned u; asm("cvt.rna.tf32.f32 %0, %1;" : "=r"(u) : "f"(x)); return u;
}
__device__ __forceinline__ float tf32f(float x) { return __uint_as_float(cvt_tf32(x)); }
__device__ __forceinline__ float phi_tf32(float x) { return tf32f(phi(x)); }

__device__ __forceinline__ void mma8(float* d, const unsigned* a, const unsigned* b) {
    asm volatile(
        "mma.sync.aligned.m16n8k8.row.col.f32.tf32.tf32.f32 "
        "{%0,%1,%2,%3},{%4,%5,%6,%7},{%8,%9},{%0,%1,%2,%3};\n"
        : "+f"(d[0]), "+f"(d[1]), "+f"(d[2]), "+f"(d[3])
        : "r"(a[0]), "r"(a[1]), "r"(a[2]), "r"(a[3]), "r"(b[0]), "r"(b[1]));
}

// A fragment from row-major [M][K] tile, stride SA. Conflict-free.
__device__ __forceinline__ void ldA76(unsigned* a, const float* tile, int r0, int k0, int lane) {
    const float* p = tile + (r0 + (lane >> 2))*SA + k0 + (lane & 3);
    a[0] = __float_as_uint(p[0]);
    a[1] = __float_as_uint(p[8*SA]);
    a[2] = __float_as_uint(p[4]);
    a[3] = __float_as_uint(p[8*SA + 4]);
}
// A fragment where tile is stored [K][M] with stride SB (i.e., A[r][c] = tile[c*SB + r]).
__device__ __forceinline__ void ldA_t72(unsigned* a, const float* tile, int r0, int k0, int lane) {
    const float* p = tile + (k0 + (lane & 3))*SB + r0 + (lane >> 2);
    a[0] = __float_as_uint(p[0]);
    a[1] = __float_as_uint(p[8]);
    a[2] = __float_as_uint(p[4*SB]);
    a[3] = __float_as_uint(p[4*SB + 8]);
}
// B fragment from [K][N] tile, stride SB. Conflict-free.
__device__ __forceinline__ void ldB_kn(unsigned* b, const float* tile, int k0, int n0, int lane) {
    const float* p = tile + (k0 + (lane & 3))*SB + n0 + (lane >> 2);
    b[0] = __float_as_uint(p[0]);
    b[1] = __float_as_uint(p[4*SB]);
}
// B fragment from [N][K] tile, stride SA (B[k][n] = tile[n*SA + k]). Conflict-free.
__device__ __forceinline__ void ldB_nk(unsigned* b, const float* tile, int k0, int n0, int lane) {
    const float* p = tile + (n0 + (lane >> 2))*SA + k0 + (lane & 3);
    b[0] = __float_as_uint(p[0]);
    b[1] = __float_as_uint(p[4]);
}

// ---------------------------------------------------------------------------
// Phase A: KV_c[d][m] = sum_s phi(k)[s][d]*v[s][m];  Ks via ones column.
// A[d][s] = k_s[s*SB + d] (k stored natural row-major, indexed transposed)
// ---------------------------------------------------------------------------
__global__ __launch_bounds__(256) void phaseA(const float* __restrict__ k,
                                              const float* __restrict__ v) {
    __shared__ float k_s[64*SB];   // [s][d]
    __shared__ float v_s[64*SB];   // [s][m], col 64 = 1.0
    int bx = blockIdx.x;
    int c = bx & 63, nh = bx >> 6;
    int n = nh / HH, h = nh % HH;
    int l0 = c * TT;
    int t = threadIdx.x, lane = t & 31, w = t >> 5;

    for (int idx = t; idx < 1024; idx += 256) {
        int s = idx >> 4, j = (idx & 15) << 2;
        size_t g = ((size_t)(n*LL + l0 + s))*HD + h*64 + j;
        float4 a = *(const float4*)(k + g);
        a.x = phi_tf32(a.x); a.y = phi_tf32(a.y); a.z = phi_tf32(a.z); a.w = phi_tf32(a.w);
        *(float4*)(k_s + s*SB + j) = a;
        float4 b = *(const float4*)(v + g);
        b.x = tf32f(b.x); b.y = tf32f(b.y); b.z = tf32f(b.z); b.w = tf32f(b.w);
        *(float4*)(v_s + s*SB + j) = b;
    }
    if (t < 64) v_s[t*SB + 64] = 1.0f;
    __syncthreads();

    int r0 = (w >> 1) * 16;         // d strip
    int odd = w & 1;
    int nbase = odd * 32;

    float acc[5][4];
#pragma unroll
    for (int i = 0; i < 5; i++)
#pragma unroll
        for (int j = 0; j < 4; j++) acc[i][j] = 0.f;

#pragma unroll
    for (int k0 = 0; k0 < 64; k0 += 8) {
        unsigned a[4]; ldA_t72(a, k_s, r0, k0, lane);
#pragma unroll
        for (int i = 0; i < 4; i++) {
            unsigned b[2]; ldB_kn(b, v_s, k0, nbase + i*8, lane);
            mma8(acc[i], a, b);
        }
        if (odd) { unsigned b[2]; ldB_kn(b, v_s, k0, 64, lane); mma8(acc[4], a, b); }
    }

    float* KVb = g_KV + (size_t)bx * 4096;
    int rowb = r0 + (lane >> 2);
#pragma unroll
    for (int i = 0; i < 4; i++) {
        int col = nbase + i*8 + (lane & 3)*2;
        *(float2*)(KVb + rowb*64 + col)     = make_float2(acc[i][0], acc[i][1]);
        *(float2*)(KVb + (rowb+8)*64 + col) = make_float2(acc[i][2], acc[i][3]);
    }
    if (odd && (lane & 3) == 0) {
        g_Ks[(size_t)bx*64 + rowb]     = acc[4][0];
        g_Ks[(size_t)bx*64 + rowb + 8] = acc[4][2];
    }
}

// ---------------------------------------------------------------------------
// Phase B: in-place exclusive prefix over chunks, float4 per thread.
// ---------------------------------------------------------------------------
__global__ __launch_bounds__(256) void phaseB() {
    int b = blockIdx.x;
    if (b < 192) {
        int gid = b*256 + threadIdx.x;                 // 49152 lanes
        int nh = gid >> 10, e4 = (gid & 1023) << 2;
        float4* base = (float4*)(g_KV + ((size_t)nh*CC)*4096 + e4);
        float4 run = make_float4(0.f, 0.f, 0.f, 0.f);
#pragma unroll 8
        for (int c = 0; c < CC; c++) {
            float4 x = base[(size_t)c*1024];
            base[(size_t)c*1024] = run;
            run.x += x.x; run.y += x.y; run.z += x.z; run.w += x.w;
        }
    } else {
        int gid = (b - 192)*256 + threadIdx.x;         // 768 lanes
        if (gid < 768) {
            int nh = gid >> 4, e4 = (gid & 15) << 2;
            float4* base = (float4*)(g_Ks + ((size_t)nh*CC)*64 + e4);
            float4 run = make_float4(0.f, 0.f, 0.f, 0.f);
#pragma unroll 8
            for (int c = 0; c < CC; c++) {
                float4 x = base[c*16];
                base[c*16] = run;
                run.x += x.x; run.y += x.y; run.z += x.z; run.w += x.w;
            }
        }
    }
}

// ---------------------------------------------------------------------------
// Phase C: P = tril(Qf Kf^T); O = Qf*S_pre + P*V; z from ones/Kpre columns.
// ---------------------------------------------------------------------------
__global__ __launch_bounds__(256) void phaseC(const float* __restrict__ q,
                                              const float* __restrict__ k,
                                              const float* __restrict__ v,
                                              float* __restrict__ out) {
    extern __shared__ float sm[];
    float* q_s = sm;                // [l][d] stride SA
    float* k_s = q_s + 64*SA;       // [s][d] stride SA  (B via [n][k] indexing)
    float* P_s = k_s + 64*SA;       // [l][s] stride SA
    float* v_s = P_s + 64*SA;       // [s][m] stride SB, col 64 = 1
    float* S_s = v_s + 64*SB;       // [d][m] stride SB, col 64 = tf32(Kpre)
    float* z_s = S_s + 64*SB;       // 64

    int bx = blockIdx.x;
    int c = bx & 63, nh = bx >> 6;
    int n = nh / HH, h = nh % HH;
    int l0 = c * TT;
    int t = threadIdx.x, lane = t & 31, w = t >> 5;

    for (int idx = t; idx < 1024; idx += 256) {
        int l = idx >> 4, j = (idx & 15) << 2;
        size_t g = ((size_t)(n*LL + l0 + l))*HD + h*64 + j;
        float4 a = *(const float4*)(q + g);
        a.x = phi_tf32(a.x); a.y = phi_tf32(a.y); a.z = phi_tf32(a.z); a.w = phi_tf32(a.w);
        *(float4*)(q_s + l*SA + j) = a;
        float4 b = *(const float4*)(k + g);
        b.x = phi_tf32(b.x); b.y = phi_tf32(b.y); b.z = phi_tf32(b.z); b.w = phi_tf32(b.w);
        *(float4*)(k_s + l*SA + j) = b;
        float4 c4 = *(const float4*)(v + g);
        c4.x = tf32f(c4.x); c4.y = tf32f(c4.y); c4.z = tf32f(c4.z); c4.w = tf32f(c4.w);
        *(float4*)(v_s + l*SB + j) = c4;
    }
    {
        const float* KVp = g_KV + (size_t)bx * 4096;
        for (int idx = t; idx < 1024; idx += 256) {
            int d = idx >> 4, j = (idx & 15) << 2;
            float4 a = *(const float4*)(KVp + d*64 + j);
            a.x = tf32f(a.x); a.y = tf32f(a.y); a.z = tf32f(a.z); a.w = tf32f(a.w);
            *(float4*)(S_s + d*SB + j) = a;
        }
    }
    if (t < 64) {
        v_s[t*SB + 64] = 1.0f;
        S_s[t*SB + 64] = tf32f(g_Ks[(size_t)bx*64 + t]);
    }
    __syncthreads();

    int r0 = (w >> 1) * 16;         // l strip
    int odd = w & 1;
    int nbase = odd * 32;

    float pacc[4][4], oacc[5][4];
#pragma unroll
    for (int i = 0; i < 4; i++)
#pragma unroll
        for (int j = 0; j < 4; j++) pacc[i][j] = 0.f;
#pragma unroll
    for (int i = 0; i < 5; i++)
#pragma unroll
        for (int j = 0; j < 4; j++) oacc[i][j] = 0.f;

    // Fused: P = Qf Kf^T  and  O = Qf S_ext
#pragma unroll
    for (int k0 = 0; k0 < 64; k0 += 8) {
        unsigned a[4]; ldA76(a, q_s, r0, k0, lane);
#pragma unroll
        for (int i = 0; i < 4; i++) {
            unsigned bk[2]; ldB_nk(bk, k_s, k0, nbase + i*8, lane);
            mma8(pacc[i], a, bk);
            unsigned bs[2]; ldB_kn(bs, S_s, k0, nbase + i*8, lane);
            mma8(oacc[i], a, bs);
        }
        if (odd) { unsigned bs[2]; ldB_kn(bs, S_s, k0, 64, lane); mma8(oacc[4], a, bs); }
    }

    // causal mask + tf32 requantize + store P
    {
        int rowb = r0 + (lane >> 2);
#pragma unroll
        for (int i = 0; i < 4; i++) {
            int colb = nbase + i*8 + (lane & 3)*2;
            P_s[rowb*SA + colb]       = tf32f((colb     <= rowb) ? pacc[i][0] : 0.f);
            P_s[rowb*SA + colb + 1]   = tf32f((colb + 1 <= rowb) ? pacc[i][1] : 0.f);
            int row1 = rowb + 8;
            P_s[row1*SA + colb]       = tf32f((colb     <= row1) ? pacc[i][2] : 0.f);
            P_s[row1*SA + colb + 1]   = tf32f((colb + 1 <= row1) ? pacc[i][3] : 0.f);
        }
    }
    __syncthreads();

    // O += P * V_ext  (ones column adds rowsum(P) into col 64)
#pragma unroll
    for (int k0 = 0; k0 < 64; k0 += 8) {
        unsigned a[4]; ldA76(a, P_s, r0, k0, lane);
#pragma unroll
        for (int i = 0; i < 4; i++) {
            unsigned b[2]; ldB_kn(b, v_s, k0, nbase + i*8, lane);
            mma8(oacc[i], a, b);
        }
        if (odd) { unsigned b[2]; ldB_kn(b, v_s, k0, 64, lane); mma8(oacc[4], a, b); }
    }

    int rowb = r0 + (lane >> 2);
    if (odd && (lane & 3) == 0) {
        z_s[rowb]     = oacc[4][0] + EPSF;
        z_s[rowb + 8] = oacc[4][2] + EPSF;
    }
    __syncthreads();

    {
        float rz0 = __frcp_rn(z_s[rowb]);
        float rz1 = __frcp_rn(z_s[rowb + 8]);
#pragma unroll
        for (int i = 0; i < 4; i++) {
            int col = nbase + i*8 + (lane & 3)*2;
            size_t g0 = ((size_t)(n*LL + l0 + rowb))*HD + h*64 + col;
            size_t g1 = ((size_t)(n*LL + l0 + rowb + 8))*HD + h*64 + col;
            *(float2*)(out + g0) = make_float2(oacc[i][0]*rz0, oacc[i][1]*rz0);
            *(float2*)(out + g1) = make_float2(oacc[i][2]*rz1, oacc[i][3]*rz1);
        }
    }
}

// ---------------------------------------------------------------------------
extern "C" void kernel_launch(void* const* d_in, const int* in_sizes, int n_in,
                              void* d_out, int out_size) {
    const float* q = (const float*)d_in[0];
    const float* k = (const float*)d_in[1];
    const float* v = (const float*)d_in[2];
    float* out = (float*)d_out;

    const int smemC = (3*64*SA + 2*64*SB + 64) * (int)sizeof(float);  // 95,488 B
    cudaFuncSetAttribute(phaseC, cudaFuncAttributeMaxDynamicSharedMemorySize, smemC);

    phaseA<<<NHNH*CC, 256>>>(k, v);
    phaseB<<<195, 256>>>();
    phaseC<<<NHNH*CC, 256, smemC>>>(q, k, v, out);
}

// round 9
// speedup vs baseline: 5.0707x; 1.4170x over previous
#include <cuda_runtime.h>
#include <cuda_fp16.h>

#define NN 4
#define LL 4096
#define HH 12
#define NHNH 48
#define TT 64
#define CC 64
#define HD 768
#define EPSF 1e-6f
#define ST 72   // half-stride for all smem tiles: 144B = 9*16B rows -> ldmatrix conflict-free

// Scratch (fp32). g_KV layout: per chunk [m][d]. phaseB prefixes in-place.
__device__ float g_KV[(size_t)NHNH*CC*4096];
__device__ float g_Ks[(size_t)NHNH*CC*64];

__device__ __forceinline__ float phi(float x) { return x > 0.f ? x + 1.f : __expf(x); }

__device__ __forceinline__ unsigned h2(float a, float b) {
    __half2 h = __floats2half2_rn(a, b);
    return *(unsigned*)&h;
}

__device__ __forceinline__ void ldsm_x4(unsigned* r, unsigned addr) {
    asm volatile("ldmatrix.sync.aligned.m8n8.x4.shared.b16 {%0,%1,%2,%3}, [%4];"
        : "=r"(r[0]), "=r"(r[1]), "=r"(r[2]), "=r"(r[3]) : "r"(addr));
}
__device__ __forceinline__ void ldsm_x4_t(unsigned* r, unsigned addr) {
    asm volatile("ldmatrix.sync.aligned.m8n8.x4.trans.shared.b16 {%0,%1,%2,%3}, [%4];"
        : "=r"(r[0]), "=r"(r[1]), "=r"(r[2]), "=r"(r[3]) : "r"(addr));
}
__device__ __forceinline__ void ldsm_x2(unsigned* r, unsigned addr) {
    asm volatile("ldmatrix.sync.aligned.m8n8.x2.shared.b16 {%0,%1}, [%2];"
        : "=r"(r[0]), "=r"(r[1]) : "r"(addr));
}
__device__ __forceinline__ void ldsm_x2_t(unsigned* r, unsigned addr) {
    asm volatile("ldmatrix.sync.aligned.m8n8.x2.trans.shared.b16 {%0,%1}, [%2];"
        : "=r"(r[0]), "=r"(r[1]) : "r"(addr));
}
__device__ __forceinline__ void mma16(float* d, const unsigned* a, const unsigned* b) {
    asm volatile(
        "mma.sync.aligned.m16n8k16.row.col.f32.f16.f16.f32 "
        "{%0,%1,%2,%3},{%4,%5,%6,%7},{%8,%9},{%0,%1,%2,%3};\n"
        : "+f"(d[0]), "+f"(d[1]), "+f"(d[2]), "+f"(d[3])
        : "r"(a[0]), "r"(a[1]), "r"(a[2]), "r"(a[3]), "r"(b[0]), "r"(b[1]));
}

// ---------------------------------------------------------------------------
// Phase A: g_KV[m][d] = sum_s v[s][m]*phi(k)[s][d]; g_Ks[d] = sum_s phi(k)[s][d]
// A = V^T via trans-ldmatrix on v_s[s][m]; B = Kf via trans-ldmatrix on k_s[s][d]
// ---------------------------------------------------------------------------
__global__ __launch_bounds__(256) void phaseA(const float* __restrict__ k,
                                              const float* __restrict__ v) {
    __shared__ alignas(16) __half k_s[64*ST];
    __shared__ alignas(16) __half v_s[64*ST];
    int bx = blockIdx.x;
    int c = bx & 63, nh = bx >> 6;
    int n = nh / HH, h = nh % HH;
    int l0 = c * TT;
    int t = threadIdx.x, lane = t & 31, w = t >> 5;

    for (int idx = t; idx < 1024; idx += 256) {
        int s = idx >> 4, j = (idx & 15) << 2;
        size_t g = ((size_t)(n*LL + l0 + s))*HD + h*64 + j;
        float4 a = *(const float4*)(k + g);
        *(uint2*)(k_s + s*ST + j) = make_uint2(h2(phi(a.x), phi(a.y)), h2(phi(a.z), phi(a.w)));
        float4 b = *(const float4*)(v + g);
        *(uint2*)(v_s + s*ST + j) = make_uint2(h2(b.x, b.y), h2(b.z, b.w));
    }
    __syncthreads();

    int r0 = (w >> 1) * 16;      // m strip
    int nb = (w & 1) * 32;       // d strip
    unsigned vb = (unsigned)__cvta_generic_to_shared(v_s);
    unsigned kb = (unsigned)__cvta_generic_to_shared(k_s);
    // A-trans lane addr: row = k0 + ((lane>>4)<<3) + (lane&7), col = r0 + ((lane>>3)&1)*8
    int at_row = ((lane >> 4) << 3) + (lane & 7);
    int at_col = r0 + ((lane >> 3) & 1) * 8;
    // B-trans x4 lane addr: row = k0 + ((lane>>3)&1)*8 + (lane&7), col = n0 + ((lane>>4)<<3)
    int bt_row = ((lane >> 3) & 1) * 8 + (lane & 7);
    int bt_col = (lane >> 4) << 3;

    float acc[4][4];
#pragma unroll
    for (int i = 0; i < 4; i++)
#pragma unroll
        for (int j = 0; j < 4; j++) acc[i][j] = 0.f;

#pragma unroll
    for (int k0 = 0; k0 < 64; k0 += 16) {
        unsigned a[4]; ldsm_x4_t(a, vb + ((k0 + at_row)*ST + at_col)*2);
        unsigned b01[4]; ldsm_x4_t(b01, kb + ((k0 + bt_row)*ST + nb + bt_col)*2);
        unsigned b23[4]; ldsm_x4_t(b23, kb + ((k0 + bt_row)*ST + nb + 16 + bt_col)*2);
        mma16(acc[0], a, b01); mma16(acc[1], a, b01 + 2);
        mma16(acc[2], a, b23); mma16(acc[3], a, b23 + 2);
    }

    float* KVb = g_KV + (size_t)bx * 4096;
    int rowb = r0 + (lane >> 2);
#pragma unroll
    for (int i = 0; i < 4; i++) {
        int col = nb + i*8 + (lane & 3)*2;
        *(float2*)(KVb + rowb*64 + col)     = make_float2(acc[i][0], acc[i][1]);
        *(float2*)(KVb + (rowb+8)*64 + col) = make_float2(acc[i][2], acc[i][3]);
    }
    if (t < 64) {
        float s0 = 0.f;
#pragma unroll 8
        for (int s = 0; s < 64; s++) s0 += __half2float(k_s[s*ST + t]);
        g_Ks[(size_t)bx*64 + t] = s0;
    }
}

// ---------------------------------------------------------------------------
// Phase B: in-place exclusive prefix over chunks, float4 per thread.
// ---------------------------------------------------------------------------
__global__ __launch_bounds__(256) void phaseB() {
    int b = blockIdx.x;
    if (b < 192) {
        int gid = b*256 + threadIdx.x;
        int nh = gid >> 10, e4 = (gid & 1023) << 2;
        float4* base = (float4*)(g_KV + ((size_t)nh*CC)*4096 + e4);
        float4 run = make_float4(0.f, 0.f, 0.f, 0.f);
#pragma unroll 8
        for (int c = 0; c < CC; c++) {
            float4 x = base[(size_t)c*1024];
            base[(size_t)c*1024] = run;
            run.x += x.x; run.y += x.y; run.z += x.z; run.w += x.w;
        }
    } else {
        int gid = (b - 192)*256 + threadIdx.x;
        if (gid < 768) {
            int nh = gid >> 4, e4 = (gid & 15) << 2;
            float4* base = (float4*)(g_Ks + ((size_t)nh*CC)*64 + e4);
            float4 run = make_float4(0.f, 0.f, 0.f, 0.f);
#pragma unroll 8
            for (int c = 0; c < CC; c++) {
                float4 x = base[c*16];
                base[c*16] = run;
                run.x += x.x; run.y += x.y; run.z += x.z; run.w += x.w;
            }
        }
    }
}

// ---------------------------------------------------------------------------
// Phase C: P = tril(Qf Kf^T); O = Qf*S_pre + P*V; z via Kpre-row / ones-col.
// ---------------------------------------------------------------------------
__global__ __launch_bounds__(256) void phaseC(const float* __restrict__ q,
                                              const float* __restrict__ k,
                                              const float* __restrict__ v,
                                              float* __restrict__ out) {
    __shared__ alignas(16) __half smb[23616];
    __shared__ float z_s[64];
    __half* q_s = smb;                 // [l][d] 64xST
    __half* k_s = smb + 4608;          // [s][d] 64xST  (B for P: [n=s][k=d])
    __half* v_s = smb + 9216;          // [s][m] 64xST, col 64 = 1
    __half* P_s = smb + 13824;         // [l][s] 64xST
    __half* S_s = smb + 18432;         // [m][d] 72xST, row 64 = Kpre, rows 65..71 = 0

    int bx = blockIdx.x;
    int c = bx & 63, nh = bx >> 6;
    int n = nh / HH, h = nh % HH;
    int l0 = c * TT;
    int t = threadIdx.x, lane = t & 31, w = t >> 5;

    for (int idx = t; idx < 1024; idx += 256) {
        int l = idx >> 4, j = (idx & 15) << 2;
        size_t g = ((size_t)(n*LL + l0 + l))*HD + h*64 + j;
        float4 a = *(const float4*)(q + g);
        *(uint2*)(q_s + l*ST + j) = make_uint2(h2(phi(a.x), phi(a.y)), h2(phi(a.z), phi(a.w)));
        float4 b = *(const float4*)(k + g);
        *(uint2*)(k_s + l*ST + j) = make_uint2(h2(phi(b.x), phi(b.y)), h2(phi(b.z), phi(b.w)));
        float4 c4 = *(const float4*)(v + g);
        *(uint2*)(v_s + l*ST + j) = make_uint2(h2(c4.x, c4.y), h2(c4.z, c4.w));
    }
    {
        const float* KVp = g_KV + (size_t)bx * 4096;
        for (int idx = t; idx < 1024; idx += 256) {
            int m = idx >> 4, j = (idx & 15) << 2;
            float4 a = *(const float4*)(KVp + m*64 + j);
            *(uint2*)(S_s + m*ST + j) = make_uint2(h2(a.x, a.y), h2(a.z, a.w));
        }
    }
    if (t < 64) {
        // v_s extra cols 64..71: col 64 = 1 (rowsum trick), rest 0
        *(uint2*)(v_s + t*ST + 64) = make_uint2(h2(1.f, 0.f), h2(0.f, 0.f));
        *(uint2*)(v_s + t*ST + 68) = make_uint2(0u, 0u);
        // S_s row 64 = Kpre, rows 65..71 = 0
        S_s[64*ST + t] = __float2half_rn(g_Ks[(size_t)bx*64 + t]);
#pragma unroll
        for (int r = 65; r < 72; r++) S_s[r*ST + t] = __ushort_as_half(0);
    }
    __syncthreads();

    int r0 = (w >> 1) * 16;    // l strip
    int odd = w & 1;
    int nb = odd * 32;
    unsigned qb = (unsigned)__cvta_generic_to_shared(q_s);
    unsigned kb = (unsigned)__cvta_generic_to_shared(k_s);
    unsigned vb = (unsigned)__cvta_generic_to_shared(v_s);
    unsigned Pb = (unsigned)__cvta_generic_to_shared(P_s);
    unsigned Sb = (unsigned)__cvta_generic_to_shared(S_s);
    // A non-trans: row = r0 + (lane&15), col = k0 + (lane>>4)*8
    int an_row = r0 + (lane & 15);
    int an_col = (lane >> 4) << 3;
    // B non-trans x4: row = n0 + ((lane>>4)<<3) + (lane&7), col = k0 + ((lane>>3)&1)*8
    int bn_row = ((lane >> 4) << 3) + (lane & 7);
    int bn_col = ((lane >> 3) & 1) << 3;
    // B trans x4: row = k0 + ((lane>>3)&1)*8 + (lane&7), col = n0 + ((lane>>4)<<3)
    int bt_row = (((lane >> 3) & 1) << 3) + (lane & 7);
    int bt_col = (lane >> 4) << 3;

    float pacc[4][4], oacc[5][4];
#pragma unroll
    for (int i = 0; i < 4; i++)
#pragma unroll
        for (int j = 0; j < 4; j++) pacc[i][j] = 0.f;
#pragma unroll
    for (int i = 0; i < 5; i++)
#pragma unroll
        for (int j = 0; j < 4; j++) oacc[i][j] = 0.f;

    // Loop 1: P = Qf Kf^T  and  O = Qf S_ext  (shared A fragments)
#pragma unroll
    for (int k0 = 0; k0 < 64; k0 += 16) {
        unsigned a[4]; ldsm_x4(a, qb + (an_row*ST + k0 + an_col)*2);
        unsigned bk[4], bk2[4];
        ldsm_x4(bk,  kb + ((nb + bn_row)*ST + k0 + bn_col)*2);
        ldsm_x4(bk2, kb + ((nb + 16 + bn_row)*ST + k0 + bn_col)*2);
        mma16(pacc[0], a, bk);  mma16(pacc[1], a, bk + 2);
        mma16(pacc[2], a, bk2); mma16(pacc[3], a, bk2 + 2);
        unsigned bs[4], bs2[4];
        ldsm_x4(bs,  Sb + ((nb + bn_row)*ST + k0 + bn_col)*2);
        ldsm_x4(bs2, Sb + ((nb + 16 + bn_row)*ST + k0 + bn_col)*2);
        mma16(oacc[0], a, bs);  mma16(oacc[1], a, bs + 2);
        mma16(oacc[2], a, bs2); mma16(oacc[3], a, bs2 + 2);
        if (odd) {
            unsigned bz[2]; ldsm_x2(bz, Sb + ((64 + (lane & 7))*ST + k0 + bn_col)*2);
            mma16(oacc[4], a, bz);
        }
    }

    // causal mask + fp16 store of P
    {
        int rowb = r0 + (lane >> 2);
#pragma unroll
        for (int i = 0; i < 4; i++) {
            int colb = nb + i*8 + (lane & 3)*2;
            float p0 = (colb     <= rowb) ? pacc[i][0] : 0.f;
            float p1 = (colb + 1 <= rowb) ? pacc[i][1] : 0.f;
            *(unsigned*)(P_s + rowb*ST + colb) = h2(p0, p1);
            int row1 = rowb + 8;
            float p2 = (colb     <= row1) ? pacc[i][2] : 0.f;
            float p3 = (colb + 1 <= row1) ? pacc[i][3] : 0.f;
            *(unsigned*)(P_s + row1*ST + colb) = h2(p2, p3);
        }
    }
    __syncthreads();

    // Loop 2: O += P * V_ext (ones column accumulates rowsum(P) into col 64)
#pragma unroll
    for (int k0 = 0; k0 < 64; k0 += 16) {
        unsigned a[4]; ldsm_x4(a, Pb + (an_row*ST + k0 + an_col)*2);
        unsigned bv[4], bv2[4];
        ldsm_x4_t(bv,  vb + ((k0 + bt_row)*ST + nb + bt_col)*2);
        ldsm_x4_t(bv2, vb + ((k0 + bt_row)*ST + nb + 16 + bt_col)*2);
        mma16(oacc[0], a, bv);  mma16(oacc[1], a, bv + 2);
        mma16(oacc[2], a, bv2); mma16(oacc[3], a, bv2 + 2);
        if (odd) {
            unsigned bz[2]; ldsm_x2_t(bz, vb + ((k0 + (lane & 15))*ST + 64)*2);
            mma16(oacc[4], a, bz);
        }
    }

    int rowb = r0 + (lane >> 2);
    if (odd && (lane & 3) == 0) {
        z_s[rowb]     = oacc[4][0] + EPSF;
        z_s[rowb + 8] = oacc[4][2] + EPSF;
    }
    __syncthreads();

    {
        float rz0 = __frcp_rn(z_s[rowb]);
        float rz1 = __frcp_rn(z_s[rowb + 8]);
#pragma unroll
        for (int i = 0; i < 4; i++) {
            int col = nb + i*8 + (lane & 3)*2;
            size_t g0 = ((size_t)(n*LL + l0 + rowb))*HD + h*64 + col;
            size_t g1 = ((size_t)(n*LL + l0 + rowb + 8))*HD + h*64 + col;
            *(float2*)(out + g0) = make_float2(oacc[i][0]*rz0, oacc[i][1]*rz0);
            *(float2*)(out + g1) = make_float2(oacc[i][2]*rz1, oacc[i][3]*rz1);
        }
    }
}

// ---------------------------------------------------------------------------
extern "C" void kernel_launch(void* const* d_in, const int* in_sizes, int n_in,
                              void* d_out, int out_size) {
    const float* q = (const float*)d_in[0];
    const float* k = (const float*)d_in[1];
    const float* v = (const float*)d_in[2];
    float* out = (float*)d_out;

    phaseA<<<NHNH*CC, 256>>>(k, v);
    phaseB<<<195, 256>>>();
    phaseC<<<NHNH*CC, 256>>>(q, k, v, out);
}

// round 10
// speedup vs baseline: 6.2409x; 1.2308x over previous
#include <cuda_runtime.h>
#include <cuda_fp16.h>

#define NN 4
#define LL 4096
#define HH 12
#define NHNH 48
#define CH 128     // chunk length
#define NC 32      // chunks per sequence
#define HD 768
#define EPSF 1e-6f
#define ST 72      // half-stride: 144B = 9*16B -> ldmatrix conflict-free

// Scratch: fp16 chunk KV sums ([m][d] per chunk); fp32 K colsums.
__device__ __half g_KVh[(size_t)NHNH*NC*4096];
__device__ float  g_Ks [(size_t)NHNH*NC*64];

__device__ __forceinline__ float phi(float x) { return x > 0.f ? x + 1.f : __expf(x); }

__device__ __forceinline__ unsigned h2(float a, float b) {
    __half2 h = __floats2half2_rn(a, b);
    return *(unsigned*)&h;
}

__device__ __forceinline__ void ldsm_x4(unsigned* r, unsigned addr) {
    asm volatile("ldmatrix.sync.aligned.m8n8.x4.shared.b16 {%0,%1,%2,%3}, [%4];"
        : "=r"(r[0]), "=r"(r[1]), "=r"(r[2]), "=r"(r[3]) : "r"(addr));
}
__device__ __forceinline__ void ldsm_x4_t(unsigned* r, unsigned addr) {
    asm volatile("ldmatrix.sync.aligned.m8n8.x4.trans.shared.b16 {%0,%1,%2,%3}, [%4];"
        : "=r"(r[0]), "=r"(r[1]), "=r"(r[2]), "=r"(r[3]) : "r"(addr));
}
__device__ __forceinline__ void ldsm_x2(unsigned* r, unsigned addr) {
    asm volatile("ldmatrix.sync.aligned.m8n8.x2.shared.b16 {%0,%1}, [%2];"
        : "=r"(r[0]), "=r"(r[1]) : "r"(addr));
}
__device__ __forceinline__ void ldsm_x2_t(unsigned* r, unsigned addr) {
    asm volatile("ldmatrix.sync.aligned.m8n8.x2.trans.shared.b16 {%0,%1}, [%2];"
        : "=r"(r[0]), "=r"(r[1]) : "r"(addr));
}
__device__ __forceinline__ void mma16(float* d, const unsigned* a, const unsigned* b) {
    asm volatile(
        "mma.sync.aligned.m16n8k16.row.col.f32.f16.f16.f32 "
        "{%0,%1,%2,%3},{%4,%5,%6,%7},{%8,%9},{%0,%1,%2,%3};\n"
        : "+f"(d[0]), "+f"(d[1]), "+f"(d[2]), "+f"(d[3])
        : "r"(a[0]), "r"(a[1]), "r"(a[2]), "r"(a[3]), "r"(b[0]), "r"(b[1]));
}

// ---------------------------------------------------------------------------
// Phase A (CH=128): g_KVh[m][d] = sum_s v[s][m]*phik[s][d]; g_Ks[d] = colsum.
// ---------------------------------------------------------------------------
__global__ __launch_bounds__(256) void phaseA(const float* __restrict__ k,
                                              const float* __restrict__ v) {
    __shared__ alignas(16) __half k_s[CH*ST];
    __shared__ alignas(16) __half v_s[CH*ST];
    int bx = blockIdx.x;
    int c = bx & 31, nh = bx >> 5;
    int n = nh / HH, h = nh % HH;
    int l0 = c * CH;
    int t = threadIdx.x, lane = t & 31, w = t >> 5;

    for (int idx = t; idx < 2048; idx += 256) {
        int s = idx >> 4, j = (idx & 15) << 2;
        size_t g = ((size_t)(n*LL + l0 + s))*HD + h*64 + j;
        float4 a = *(const float4*)(k + g);
        *(uint2*)(k_s + s*ST + j) = make_uint2(h2(phi(a.x), phi(a.y)), h2(phi(a.z), phi(a.w)));
        float4 b = *(const float4*)(v + g);
        *(uint2*)(v_s + s*ST + j) = make_uint2(h2(b.x, b.y), h2(b.z, b.w));
    }
    __syncthreads();

    int r0 = (w >> 1) * 16;      // m strip
    int nb = (w & 1) * 32;       // d strip
    unsigned vb = (unsigned)__cvta_generic_to_shared(v_s);
    unsigned kb = (unsigned)__cvta_generic_to_shared(k_s);
    int at_row = ((lane >> 4) << 3) + (lane & 7);
    int at_col = r0 + ((lane >> 3) & 1) * 8;
    int bt_row = ((lane >> 3) & 1) * 8 + (lane & 7);
    int bt_col = (lane >> 4) << 3;

    float acc[4][4];
#pragma unroll
    for (int i = 0; i < 4; i++)
#pragma unroll
        for (int j = 0; j < 4; j++) acc[i][j] = 0.f;

#pragma unroll
    for (int k0 = 0; k0 < 128; k0 += 16) {
        unsigned a[4]; ldsm_x4_t(a, vb + ((k0 + at_row)*ST + at_col)*2);
        unsigned b01[4]; ldsm_x4_t(b01, kb + ((k0 + bt_row)*ST + nb + bt_col)*2);
        unsigned b23[4]; ldsm_x4_t(b23, kb + ((k0 + bt_row)*ST + nb + 16 + bt_col)*2);
        mma16(acc[0], a, b01); mma16(acc[1], a, b01 + 2);
        mma16(acc[2], a, b23); mma16(acc[3], a, b23 + 2);
    }

    __half* KVb = g_KVh + (size_t)bx * 4096;
    int rowb = r0 + (lane >> 2);
#pragma unroll
    for (int i = 0; i < 4; i++) {
        int col = nb + i*8 + (lane & 3)*2;
        *(unsigned*)(KVb + rowb*64 + col)     = h2(acc[i][0], acc[i][1]);
        *(unsigned*)(KVb + (rowb+8)*64 + col) = h2(acc[i][2], acc[i][3]);
    }
    if (t < 64) {
        float s0 = 0.f;
#pragma unroll 8
        for (int s = 0; s < 128; s++) s0 += __half2float(k_s[s*ST + t]);
        g_Ks[(size_t)bx*64 + t] = s0;
    }
}

// ---------------------------------------------------------------------------
// Phase B: in-place exclusive prefix over NC chunks (fp32 accumulation).
// ---------------------------------------------------------------------------
__global__ __launch_bounds__(256) void phaseB() {
    int b = blockIdx.x;
    int t = threadIdx.x;
    if (b < 192) {
        int gid = b*256 + t;                    // 49152 = 48 nh * 1024 uint2-lanes
        int nh = gid >> 10, e = gid & 1023;
        uint2* base = (uint2*)(g_KVh + (size_t)nh*NC*4096) + e;
        float2 ra = make_float2(0.f, 0.f), rb = make_float2(0.f, 0.f);
#pragma unroll 8
        for (int c = 0; c < NC; c++) {
            uint2 x = base[c*1024];
            float2 f0 = __half22float2(*(__half2*)&x.x);
            float2 f1 = __half22float2(*(__half2*)&x.y);
            base[c*1024] = make_uint2(h2(ra.x, ra.y), h2(rb.x, rb.y));
            ra.x += f0.x; ra.y += f0.y; rb.x += f1.x; rb.y += f1.y;
        }
    } else {
        int gid = (b - 192)*256 + t;            // 768 = 48 nh * 16 float4-lanes
        if (gid < 768) {
            int nh = gid >> 4, e4 = (gid & 15) << 2;
            float4* base = (float4*)(g_Ks + (size_t)nh*NC*64 + e4);
            float4 run = make_float4(0.f, 0.f, 0.f, 0.f);
#pragma unroll 8
            for (int c = 0; c < NC; c++) {
                float4 x = base[c*16];
                base[c*16] = run;
                run.x += x.x; run.y += x.y; run.z += x.z; run.w += x.w;
            }
        }
    }
}

// ---------------------------------------------------------------------------
// Phase C (CH=128, two 64-row sub-tiles sharing in-smem state):
//   per tile: P = tril(Qt Kt^T); O = Qt*S_ext + P*Vt_ext; out = O/z
//   between tiles: S += V0^T phiK0 (mma), Kpre += colsum phiK0
// ---------------------------------------------------------------------------
__global__ __launch_bounds__(256) void phaseC(const float* __restrict__ q,
                                              const float* __restrict__ k,
                                              const float* __restrict__ v,
                                              float* __restrict__ out) {
    extern __shared__ __align__(16) __half smb[];
    __half* q_s = smb;              // [l][d]  128 x ST
    __half* k_s = smb + 9216;       // [s][d]  128 x ST
    __half* v_s = smb + 18432;      // [s][m]  128 x ST, col 64 = 1, 65..71 = 0
    __half* P_s = smb + 27648;      // [l][s]  64 x ST (per sub-tile)
    __half* S_s = smb + 32256;      // [m][d]  72 x ST, row 64 = Kpre, 65..71 = 0
    float*  z_s = (float*)(smb + 37440);  // 64

    int bx = blockIdx.x;
    int c = bx & 31, nh = bx >> 5;
    int n = nh / HH, h = nh % HH;
    int l0 = c * CH;
    int t = threadIdx.x, lane = t & 31, w = t >> 5;

    for (int idx = t; idx < 2048; idx += 256) {
        int l = idx >> 4, j = (idx & 15) << 2;
        size_t g = ((size_t)(n*LL + l0 + l))*HD + h*64 + j;
        float4 a = *(const float4*)(q + g);
        *(uint2*)(q_s + l*ST + j) = make_uint2(h2(phi(a.x), phi(a.y)), h2(phi(a.z), phi(a.w)));
        float4 b = *(const float4*)(k + g);
        *(uint2*)(k_s + l*ST + j) = make_uint2(h2(phi(b.x), phi(b.y)), h2(phi(b.z), phi(b.w)));
        float4 c4 = *(const float4*)(v + g);
        *(uint2*)(v_s + l*ST + j) = make_uint2(h2(c4.x, c4.y), h2(c4.z, c4.w));
    }
    {
        const __half* KVp = g_KVh + (size_t)bx * 4096;
        for (int idx = t; idx < 512; idx += 256) {
            int m = idx >> 3, j = (idx & 7) << 3;
            *(uint4*)(S_s + m*ST + j) = *(const uint4*)(KVp + m*64 + j);
        }
    }
    if (t < 128) {
        *(uint2*)(v_s + t*ST + 64) = make_uint2(h2(1.f, 0.f), 0u);
        *(uint2*)(v_s + t*ST + 68) = make_uint2(0u, 0u);
    }
    for (int idx = t; idx < 448; idx += 256)
        S_s[(65 + (idx >> 6))*ST + (idx & 63)] = __ushort_as_half(0);
    if (t < 64) S_s[64*ST + t] = __float2half_rn(g_Ks[(size_t)bx*64 + t]);
    __syncthreads();

    int r0 = (w >> 1) * 16;     // l strip (and m strip for S-update)
    int odd = w & 1;
    int nb = odd * 32;
    unsigned qb = (unsigned)__cvta_generic_to_shared(q_s);
    unsigned kb = (unsigned)__cvta_generic_to_shared(k_s);
    unsigned vb = (unsigned)__cvta_generic_to_shared(v_s);
    unsigned Pb = (unsigned)__cvta_generic_to_shared(P_s);
    unsigned Sb = (unsigned)__cvta_generic_to_shared(S_s);
    int an_row = r0 + (lane & 15);
    int an_col = (lane >> 4) << 3;
    int bn_row = ((lane >> 4) << 3) + (lane & 7);
    int bn_col = ((lane >> 3) & 1) << 3;
    int bt_row = (((lane >> 3) & 1) << 3) + (lane & 7);
    int bt_col = (lane >> 4) << 3;
    int at_row = ((lane >> 4) << 3) + (lane & 7);
    int at_col = r0 + ((lane >> 3) & 1) * 8;
    int rowb = r0 + (lane >> 2);

    for (int tile = 0; tile < 2; tile++) {
        int ro = tile << 6;

        float pacc[4][4], oacc[5][4];
#pragma unroll
        for (int i = 0; i < 4; i++)
#pragma unroll
            for (int j = 0; j < 4; j++) pacc[i][j] = 0.f;
#pragma unroll
        for (int i = 0; i < 5; i++)
#pragma unroll
            for (int j = 0; j < 4; j++) oacc[i][j] = 0.f;

        // Loop 1: P = Qt Kt^T  and  O = Qt S_ext (z-part via Kpre row 64)
#pragma unroll
        for (int k0 = 0; k0 < 64; k0 += 16) {
            unsigned a[4]; ldsm_x4(a, qb + ((ro + an_row)*ST + k0 + an_col)*2);
            unsigned bk[4], bk2[4];
            ldsm_x4(bk,  kb + ((ro + nb + bn_row)*ST + k0 + bn_col)*2);
            ldsm_x4(bk2, kb + ((ro + nb + 16 + bn_row)*ST + k0 + bn_col)*2);
            mma16(pacc[0], a, bk);  mma16(pacc[1], a, bk + 2);
            mma16(pacc[2], a, bk2); mma16(pacc[3], a, bk2 + 2);
            unsigned bs[4], bs2[4];
            ldsm_x4(bs,  Sb + ((nb + bn_row)*ST + k0 + bn_col)*2);
            ldsm_x4(bs2, Sb + ((nb + 16 + bn_row)*ST + k0 + bn_col)*2);
            mma16(oacc[0], a, bs);  mma16(oacc[1], a, bs + 2);
            mma16(oacc[2], a, bs2); mma16(oacc[3], a, bs2 + 2);
            if (odd) {
                unsigned bz[2]; ldsm_x2(bz, Sb + ((64 + (lane & 7))*ST + k0 + bn_col)*2);
                mma16(oacc[4], a, bz);
            }
        }

        // causal mask (relative indices) + fp16 store of P
#pragma unroll
        for (int i = 0; i < 4; i++) {
            int colb = nb + i*8 + (lane & 3)*2;
            float p0 = (colb     <= rowb) ? pacc[i][0] : 0.f;
            float p1 = (colb + 1 <= rowb) ? pacc[i][1] : 0.f;
            *(unsigned*)(P_s + rowb*ST + colb) = h2(p0, p1);
            int row1 = rowb + 8;
            float p2 = (colb     <= row1) ? pacc[i][2] : 0.f;
            float p3 = (colb + 1 <= row1) ? pacc[i][3] : 0.f;
            *(unsigned*)(P_s + row1*ST + colb) = h2(p2, p3);
        }
        __syncthreads();

        // Loop 2: O += P * Vt_ext (ones col -> rowsum(P) joins z)
#pragma unroll
        for (int k0 = 0; k0 < 64; k0 += 16) {
            unsigned a[4]; ldsm_x4(a, Pb + (an_row*ST + k0 + an_col)*2);
            unsigned bv[4], bv2[4];
            ldsm_x4_t(bv,  vb + ((ro + k0 + bt_row)*ST + nb + bt_col)*2);
            ldsm_x4_t(bv2, vb + ((ro + k0 + bt_row)*ST + nb + 16 + bt_col)*2);
            mma16(oacc[0], a, bv);  mma16(oacc[1], a, bv + 2);
            mma16(oacc[2], a, bv2); mma16(oacc[3], a, bv2 + 2);
            if (odd) {
                unsigned bz[2]; ldsm_x2_t(bz, vb + ((ro + k0 + (lane & 15))*ST + 64)*2);
                mma16(oacc[4], a, bz);
            }
        }

        if (odd && (lane & 3) == 0) {
            z_s[rowb]     = oacc[4][0] + EPSF;
            z_s[rowb + 8] = oacc[4][2] + EPSF;
        }
        __syncthreads();

        {
            float rz0 = __frcp_rn(z_s[rowb]);
            float rz1 = __frcp_rn(z_s[rowb + 8]);
#pragma unroll
            for (int i = 0; i < 4; i++) {
                int col = nb + i*8 + (lane & 3)*2;
                size_t g0 = ((size_t)(n*LL + l0 + ro + rowb))*HD + h*64 + col;
                size_t g1 = ((size_t)(n*LL + l0 + ro + rowb + 8))*HD + h*64 + col;
                *(float2*)(out + g0) = make_float2(oacc[i][0]*rz0, oacc[i][1]*rz0);
                *(float2*)(out + g1) = make_float2(oacc[i][2]*rz1, oacc[i][3]*rz1);
            }
        }

        if (tile == 0) {
            // S += V0^T phiK0 (rows m = r0 strip, cols d = nb strip)
            float uacc[4][4];
#pragma unroll
            for (int i = 0; i < 4; i++)
#pragma unroll
                for (int j = 0; j < 4; j++) uacc[i][j] = 0.f;
#pragma unroll
            for (int k0 = 0; k0 < 64; k0 += 16) {
                unsigned ua[4]; ldsm_x4_t(ua, vb + ((k0 + at_row)*ST + at_col)*2);
                unsigned ub[4], ub2[4];
                ldsm_x4_t(ub,  kb + ((k0 + bt_row)*ST + nb + bt_col)*2);
                ldsm_x4_t(ub2, kb + ((k0 + bt_row)*ST + nb + 16 + bt_col)*2);
                mma16(uacc[0], ua, ub);  mma16(uacc[1], ua, ub + 2);
                mma16(uacc[2], ua, ub2); mma16(uacc[3], ua, ub2 + 2);
            }
#pragma unroll
            for (int i = 0; i < 4; i++) {
                int col = nb + i*8 + (lane & 3)*2;
                unsigned* p0 = (unsigned*)(S_s + rowb*ST + col);
                float2 f0 = __half22float2(*(__half2*)p0);
                *p0 = h2(f0.x + uacc[i][0], f0.y + uacc[i][1]);
                unsigned* p1 = (unsigned*)(S_s + (rowb + 8)*ST + col);
                float2 f1 = __half22float2(*(__half2*)p1);
                *p1 = h2(f1.x + uacc[i][2], f1.y + uacc[i][3]);
            }
            if (t < 64) {
                float s0 = 0.f;
#pragma unroll 8
                for (int s = 0; s < 64; s++) s0 += __half2float(k_s[s*ST + t]);
                S_s[64*ST + t] = __float2half_rn(__half2float(S_s[64*ST + t]) + s0);
            }
            __syncthreads();
        }
    }
}

// ---------------------------------------------------------------------------
extern "C" void kernel_launch(void* const* d_in, const int* in_sizes, int n_in,
                              void* d_out, int out_size) {
    const float* q = (const float*)d_in[0];
    const float* k = (const float*)d_in[1];
    const float* v = (const float*)d_in[2];
    float* out = (float*)d_out;

    const int smemC = 37440*2 + 64*4;   // 75,136 B
    cudaFuncSetAttribute(phaseC, cudaFuncAttributeMaxDynamicSharedMemorySize, smemC);

    phaseA<<<NHNH*NC, 256>>>(k, v);
    phaseB<<<195, 256>>>();
    phaseC<<<NHNH*NC, 256, smemC>>>(q, k, v, out);
}

// round 12
// speedup vs baseline: 7.4059x; 1.1867x over previous
#include <cuda_runtime.h>
#include <cuda_fp16.h>

#define NN 4
#define LL 4096
#define HH 12
#define NHNH 48
#define CH 128     // chunk length
#define NC 32      // chunks per sequence
#define HD 768
#define EPSF 1e-6f
#define ST 72      // half-stride: 144B = 9*16B -> ldmatrix conflict-free

// Scratch: inclusive chunk prefixes (fp16 [m][d]); fp32 K colsum prefixes; flags.
__device__ __half g_KVh[(size_t)NHNH*NC*4096];
__device__ float  g_Ks [(size_t)NHNH*NC*64];
__device__ int    g_flag[NHNH*NC];

__device__ __forceinline__ float phi(float x) { return x > 0.f ? x + 1.f : __expf(x); }

__device__ __forceinline__ unsigned h2(float a, float b) {
    __half2 h = __floats2half2_rn(a, b);
    return *(unsigned*)&h;
}

__device__ __forceinline__ void ldsm_x4(unsigned* r, unsigned addr) {
    asm volatile("ldmatrix.sync.aligned.m8n8.x4.shared.b16 {%0,%1,%2,%3}, [%4];"
        : "=r"(r[0]), "=r"(r[1]), "=r"(r[2]), "=r"(r[3]) : "r"(addr));
}
__device__ __forceinline__ void ldsm_x4_t(unsigned* r, unsigned addr) {
    asm volatile("ldmatrix.sync.aligned.m8n8.x4.trans.shared.b16 {%0,%1,%2,%3}, [%4];"
        : "=r"(r[0]), "=r"(r[1]), "=r"(r[2]), "=r"(r[3]) : "r"(addr));
}
__device__ __forceinline__ void ldsm_x2(unsigned* r, unsigned addr) {
    asm volatile("ldmatrix.sync.aligned.m8n8.x2.shared.b16 {%0,%1}, [%2];"
        : "=r"(r[0]), "=r"(r[1]) : "r"(addr));
}
__device__ __forceinline__ void ldsm_x2_t(unsigned* r, unsigned addr) {
    asm volatile("ldmatrix.sync.aligned.m8n8.x2.trans.shared.b16 {%0,%1}, [%2];"
        : "=r"(r[0]), "=r"(r[1]) : "r"(addr));
}
__device__ __forceinline__ void mma16(float* d, const unsigned* a, const unsigned* b) {
    asm volatile(
        "mma.sync.aligned.m16n8k16.row.col.f32.f16.f16.f32 "
        "{%0,%1,%2,%3},{%4,%5,%6,%7},{%8,%9},{%0,%1,%2,%3};\n"
        : "+f"(d[0]), "+f"(d[1]), "+f"(d[2]), "+f"(d[3])
        : "r"(a[0]), "r"(a[1]), "r"(a[2]), "r"(a[3]), "r"(b[0]), "r"(b[1]));
}

// ---------------------------------------------------------------------------
// Reset flags (device globals persist across graph replays)
// ---------------------------------------------------------------------------
__global__ void resetK() {
    int i = blockIdx.x * 256 + threadIdx.x;
    if (i < NHNH*NC) g_flag[i] = 0;
}

// ---------------------------------------------------------------------------
// Fused single-pass chained scan + output.  bid = c*NHNH + nh.
// ---------------------------------------------------------------------------
__global__ __launch_bounds__(256) void fusedK(const float* __restrict__ q,
                                              const float* __restrict__ k,
                                              const float* __restrict__ v,
                                              float* __restrict__ out) {
    extern __shared__ __align__(16) __half smb[];
    __half* q_s = smb;              // [l][d]  128 x ST
    __half* k_s = smb + 9216;       // [s][d]  128 x ST
    __half* v_s = smb + 18432;      // [s][m]  128 x ST, col 64 = 1, 65..71 = 0
    __half* P_s = smb + 27648;      // [l][s]  64 x ST
    __half* S_s = smb + 32256;      // [m][d]  72 x ST, row 64 = Kpre, 65..71 = 0
    float*  z_s = (float*)(smb + 37440);  // 64

    int bid = blockIdx.x;
    int c = bid / NHNH, nh = bid - c*NHNH;
    int n = nh / HH, h = nh % HH;
    int l0 = c * CH;
    int t = threadIdx.x, lane = t & 31, w = t >> 5;

    // ---- stage inputs (phi on q,k; fp16) ----
    for (int idx = t; idx < 2048; idx += 256) {
        int l = idx >> 4, j = (idx & 15) << 2;
        size_t g = ((size_t)(n*LL + l0 + l))*HD + h*64 + j;
        float4 a = *(const float4*)(q + g);
        *(uint2*)(q_s + l*ST + j) = make_uint2(h2(phi(a.x), phi(a.y)), h2(phi(a.z), phi(a.w)));
        float4 b = *(const float4*)(k + g);
        *(uint2*)(k_s + l*ST + j) = make_uint2(h2(phi(b.x), phi(b.y)), h2(phi(b.z), phi(b.w)));
        float4 c4 = *(const float4*)(v + g);
        *(uint2*)(v_s + l*ST + j) = make_uint2(h2(c4.x, c4.y), h2(c4.z, c4.w));
    }
    if (t < 128) {
        *(uint2*)(v_s + t*ST + 64) = make_uint2(h2(1.f, 0.f), 0u);
        *(uint2*)(v_s + t*ST + 68) = make_uint2(0u, 0u);
    }
    for (int idx = t; idx < 448; idx += 256)
        S_s[(65 + (idx >> 6))*ST + (idx & 63)] = __ushort_as_half(0);
    __syncthreads();

    // warp strips / lane addressing
    int r0 = (w >> 1) * 16;     // m / l strip
    int odd = w & 1;
    int nb = odd * 32;          // d / s / m-col strip
    unsigned qb = (unsigned)__cvta_generic_to_shared(q_s);
    unsigned kb = (unsigned)__cvta_generic_to_shared(k_s);
    unsigned vb = (unsigned)__cvta_generic_to_shared(v_s);
    unsigned Pb = (unsigned)__cvta_generic_to_shared(P_s);
    unsigned Sb = (unsigned)__cvta_generic_to_shared(S_s);
    int an_row = r0 + (lane & 15);
    int an_col = (lane >> 4) << 3;
    int bn_row = ((lane >> 4) << 3) + (lane & 7);
    int bn_col = ((lane >> 3) & 1) << 3;
    int bt_row = (((lane >> 3) & 1) << 3) + (lane & 7);
    int bt_col = (lane >> 4) << 3;
    int at_row = ((lane >> 4) << 3) + (lane & 7);
    int at_col = r0 + ((lane >> 3) & 1) * 8;
    int rowb = r0 + (lane >> 2);

    // ---- local aggregate: KVagg[m][d] = sum_{s<128} v[s][m]*phik[s][d] ----
    float agg[4][4];
#pragma unroll
    for (int i = 0; i < 4; i++)
#pragma unroll
        for (int j = 0; j < 4; j++) agg[i][j] = 0.f;
#pragma unroll
    for (int k0 = 0; k0 < 128; k0 += 16) {
        unsigned a[4]; ldsm_x4_t(a, vb + ((k0 + at_row)*ST + at_col)*2);
        unsigned b01[4]; ldsm_x4_t(b01, kb + ((k0 + bt_row)*ST + nb + bt_col)*2);
        unsigned b23[4]; ldsm_x4_t(b23, kb + ((k0 + bt_row)*ST + nb + 16 + bt_col)*2);
        mma16(agg[0], a, b01); mma16(agg[1], a, b01 + 2);
        mma16(agg[2], a, b23); mma16(agg[3], a, b23 + 2);
    }
    float ksagg = 0.f;
    if (t < 64) {
#pragma unroll 8
        for (int s = 0; s < 128; s++) ksagg += __half2float(k_s[s*ST + t]);
    }

    // ---- wait for predecessor, stage S_pre, publish inclusive ----
    if (c > 0) {
        if (t == 0) {
            const int* fp = g_flag + bid - NHNH;
            int f;
            do {
                asm volatile("ld.global.acquire.gpu.b32 %0, [%1];" : "=r"(f) : "l"(fp));
                if (!f) __nanosleep(40);
            } while (!f);
        }
        __syncthreads();
        const __half* pred = g_KVh + (size_t)(bid - NHNH) * 4096;
        __half* mine = g_KVh + (size_t)bid * 4096;
#pragma unroll
        for (int i = 0; i < 4; i++) {
            int col = nb + i*8 + (lane & 3)*2;
            unsigned p0 = __ldcg((const unsigned*)(pred + rowb*64 + col));
            unsigned p1 = __ldcg((const unsigned*)(pred + (rowb+8)*64 + col));
            *(unsigned*)(S_s + rowb*ST + col)     = p0;
            *(unsigned*)(S_s + (rowb+8)*ST + col) = p1;
            float2 f0 = __half22float2(*(__half2*)&p0);
            float2 f1 = __half22float2(*(__half2*)&p1);
            *(unsigned*)(mine + rowb*64 + col)     = h2(f0.x + agg[i][0], f0.y + agg[i][1]);
            *(unsigned*)(mine + (rowb+8)*64 + col) = h2(f1.x + agg[i][2], f1.y + agg[i][3]);
        }
        if (t < 64) {
            float pks = __ldcg(g_Ks + (size_t)(bid - NHNH)*64 + t);
            S_s[64*ST + t] = __float2half_rn(pks);
            g_Ks[(size_t)bid*64 + t] = pks + ksagg;
        }
    } else {
        __half* mine = g_KVh + (size_t)bid * 4096;
#pragma unroll
        for (int i = 0; i < 4; i++) {
            int col = nb + i*8 + (lane & 3)*2;
            *(unsigned*)(S_s + rowb*ST + col)     = 0u;
            *(unsigned*)(S_s + (rowb+8)*ST + col) = 0u;
            *(unsigned*)(mine + rowb*64 + col)     = h2(agg[i][0], agg[i][1]);
            *(unsigned*)(mine + (rowb+8)*64 + col) = h2(agg[i][2], agg[i][3]);
        }
        if (t < 64) {
            S_s[64*ST + t] = __ushort_as_half(0);
            g_Ks[(size_t)bid*64 + t] = ksagg;
        }
    }
    __syncthreads();    // all strips staged in S_s + gmem inclusive complete
    if (t == 0)
        asm volatile("st.global.release.gpu.b32 [%0], %1;" :: "l"(g_flag + bid), "r"(1));

    // ---- two 64-row sub-tiles sharing in-smem state ----
    for (int tile = 0; tile < 2; tile++) {
        int ro = tile << 6;

        float pacc[4][4], oacc[5][4];
#pragma unroll
        for (int i = 0; i < 4; i++)
#pragma unroll
            for (int j = 0; j < 4; j++) pacc[i][j] = 0.f;
#pragma unroll
        for (int i = 0; i < 5; i++)
#pragma unroll
            for (int j = 0; j < 4; j++) oacc[i][j] = 0.f;

        // Loop 1: P = Qt Kt^T  and  O = Qt S_ext (z-part via Kpre row 64)
#pragma unroll
        for (int k0 = 0; k0 < 64; k0 += 16) {
            unsigned a[4]; ldsm_x4(a, qb + ((ro + an_row)*ST + k0 + an_col)*2);
            unsigned bk[4], bk2[4];
            ldsm_x4(bk,  kb + ((ro + nb + bn_row)*ST + k0 + bn_col)*2);
            ldsm_x4(bk2, kb + ((ro + nb + 16 + bn_row)*ST + k0 + bn_col)*2);
            mma16(pacc[0], a, bk);  mma16(pacc[1], a, bk + 2);
            mma16(pacc[2], a, bk2); mma16(pacc[3], a, bk2 + 2);
            unsigned bs[4], bs2[4];
            ldsm_x4(bs,  Sb + ((nb + bn_row)*ST + k0 + bn_col)*2);
            ldsm_x4(bs2, Sb + ((nb + 16 + bn_row)*ST + k0 + bn_col)*2);
            mma16(oacc[0], a, bs);  mma16(oacc[1], a, bs + 2);
            mma16(oacc[2], a, bs2); mma16(oacc[3], a, bs2 + 2);
            if (odd) {
                unsigned bz[2]; ldsm_x2(bz, Sb + ((64 + (lane & 7))*ST + k0 + bn_col)*2);
                mma16(oacc[4], a, bz);
            }
        }

        // causal mask (relative indices) + fp16 store of P
#pragma unroll
        for (int i = 0; i < 4; i++) {
            int colb = nb + i*8 + (lane & 3)*2;
            float p0 = (colb     <= rowb) ? pacc[i][0] : 0.f;
            float p1 = (colb + 1 <= rowb) ? pacc[i][1] : 0.f;
            *(unsigned*)(P_s + rowb*ST + colb) = h2(p0, p1);
            int row1 = rowb + 8;
            float p2 = (colb     <= row1) ? pacc[i][2] : 0.f;
            float p3 = (colb + 1 <= row1) ? pacc[i][3] : 0.f;
            *(unsigned*)(P_s + row1*ST + colb) = h2(p2, p3);
        }
        __syncthreads();

        // Loop 2: O += P * Vt_ext (ones col -> rowsum(P) joins z)
#pragma unroll
        for (int k0 = 0; k0 < 64; k0 += 16) {
            unsigned a[4]; ldsm_x4(a, Pb + (an_row*ST + k0 + an_col)*2);
            unsigned bv[4], bv2[4];
            ldsm_x4_t(bv,  vb + ((ro + k0 + bt_row)*ST + nb + bt_col)*2);
            ldsm_x4_t(bv2, vb + ((ro + k0 + bt_row)*ST + nb + 16 + bt_col)*2);
            mma16(oacc[0], a, bv);  mma16(oacc[1], a, bv + 2);
            mma16(oacc[2], a, bv2); mma16(oacc[3], a, bv2 + 2);
            if (odd) {
                unsigned bz[2]; ldsm_x2_t(bz, vb + ((ro + k0 + (lane & 15))*ST + 64)*2);
                mma16(oacc[4], a, bz);
            }
        }

        if (odd && (lane & 3) == 0) {
            z_s[rowb]     = oacc[4][0] + EPSF;
            z_s[rowb + 8] = oacc[4][2] + EPSF;
        }
        __syncthreads();

        {
            float rz0 = __frcp_rn(z_s[rowb]);
            float rz1 = __frcp_rn(z_s[rowb + 8]);
#pragma unroll
            for (int i = 0; i < 4; i++) {
                int col = nb + i*8 + (lane & 3)*2;
                size_t g0 = ((size_t)(n*LL + l0 + ro + rowb))*HD + h*64 + col;
                size_t g1 = ((size_t)(n*LL + l0 + ro + rowb + 8))*HD + h*64 + col;
                *(float2*)(out + g0) = make_float2(oacc[i][0]*rz0, oacc[i][1]*rz0);
                *(float2*)(out + g1) = make_float2(oacc[i][2]*rz1, oacc[i][3]*rz1);
            }
        }

        if (tile == 0) {
            // S += V0^T phiK0; Kpre += colsum phiK0
            float uacc[4][4];
#pragma unroll
            for (int i = 0; i < 4; i++)
#pragma unroll
                for (int j = 0; j < 4; j++) uacc[i][j] = 0.f;
#pragma unroll
            for (int k0 = 0; k0 < 64; k0 += 16) {
                unsigned ua[4]; ldsm_x4_t(ua, vb + ((k0 + at_row)*ST + at_col)*2);
                unsigned ub[4], ub2[4];
                ldsm_x4_t(ub,  kb + ((k0 + bt_row)*ST + nb + bt_col)*2);
                ldsm_x4_t(ub2, kb + ((k0 + bt_row)*ST + nb + 16 + bt_col)*2);
                mma16(uacc[0], ua, ub);  mma16(uacc[1], ua, ub + 2);
                mma16(uacc[2], ua, ub2); mma16(uacc[3], ua, ub2 + 2);
            }
#pragma unroll
            for (int i = 0; i < 4; i++) {
                int col = nb + i*8 + (lane & 3)*2;
                unsigned* p0 = (unsigned*)(S_s + rowb*ST + col);
                float2 f0 = __half22float2(*(__half2*)p0);
                *p0 = h2(f0.x + uacc[i][0], f0.y + uacc[i][1]);
                unsigned* p1 = (unsigned*)(S_s + (rowb + 8)*ST + col);
                float2 f1 = __half22float2(*(__half2*)p1);
                *p1 = h2(f1.x + uacc[i][2], f1.y + uacc[i][3]);
            }
            if (t < 64) {
                float s0 = 0.f;
#pragma unroll 8
                for (int s = 0; s < 64; s++) s0 += __half2float(k_s[s*ST + t]);
                S_s[64*ST + t] = __float2half_rn(__half2float(S_s[64*ST + t]) + s0);
            }
            __syncthreads();
        }
    }
}

// ---------------------------------------------------------------------------
extern "C" void kernel_launch(void* const* d_in, const int* in_sizes, int n_in,
                              void* d_out, int out_size) {
    const float* q = (const float*)d_in[0];
    const float* k = (const float*)d_in[1];
    const float* v = (const float*)d_in[2];
    float* out = (float*)d_out;

    const int smemC = 37440*2 + 64*4;   // 75,136 B
    cudaFuncSetAttribute(fusedK, cudaFuncAttributeMaxDynamicSharedMemorySize, smemC);

    resetK<<<6, 256>>>();
    fusedK<<<NHNH*NC, 256, smemC>>>(q, k, v, out);
}